// round 12
// baseline (speedup 1.0000x reference)
#include <cuda_runtime.h>
#include <cuda_fp16.h>
#include <math.h>
#include <stdint.h>

// ---------------------------------------------------------------------------
// VQ-VAE forward. T=30, B=1024, D_POSE=135, H=512, K_CODES=512.
// Activations [b, position, channel] -> every conv/convT/linear is a row-major
// GEMM C[M,N] = A[M,K] * B'[N,K]^T on mma.sync.m16n8k16 f16 with 3xFP16
// hi/lo split (err ~2^-24).
// R12: BN normalize+ReLU+split fused into the CONSUMER GEMM's A-load
// (stats come from the producer GEMM's fused epilogue). bn_norm2 is gone.
// ---------------------------------------------------------------------------

#define EPSV 1e-5f

// ======================= fp32 scratch ======================================
constexpr long O_E1R = 0;                        // 6144 x 512 (raw, pre-BN)
constexpr long O_E2R = O_E1R + 6144L * 512;      // 2048 x 512
constexpr long O_ZR  = O_E2R + 2048L * 512;      // 1024 x 512
constexpr long O_D1R = O_ZR  + 1024L * 512;      // 1024 x 1024
constexpr long O_D2R = O_D1R + 1024L * 1024;     // 2048 x 1536
constexpr long O_D3R = O_D2R + 2048L * 1536;     // 6144 x 2560
constexpr long O_SC  = O_D3R + 6144L * 2560;     // 1024 x 512
constexpr long O_CN  = O_SC  + 1024L * 512;      // 512
constexpr long O_STAT= O_CN  + 512;              // 6 x 2 x 512
constexpr long O_LOSS= O_STAT+ 6L * 2 * 512;
constexpr long O_CNT = O_LOSS+ 512;
constexpr long TOTALF= O_CNT + 512;

__device__ float g_buf[TOTALF];

// ======================= f16 split scratch (hi then lo per buffer) =========
constexpr long H_WE1 = 0;                          // [512,2560]
constexpr long H_WE2 = H_WE1 + 2L * 512 * 2560;    // [512,1536]
constexpr long H_WE3 = H_WE2 + 2L * 512 * 1536;    // [512,1024]
constexpr long H_WD1 = H_WE3 + 2L * 512 * 1024;    // [1024,512]
constexpr long H_WD2 = H_WD1 + 2L * 1024 * 512;    // [1536,512]
constexpr long H_WD3 = H_WD2 + 2L * 1536 * 512;    // [2560,512]
constexpr long H_WIT = H_WD3 + 2L * 2560 * 512;    // [512,160]
constexpr long H_WQT = H_WIT + 2L * 512 * 160;     // [512,512]
constexpr long H_WOT = H_WQT + 2L * 512 * 512;     // [135,512]
constexpr long H_CB  = H_WOT + 2L * 135 * 512;     // [512,512]
constexpr long H_XIN = H_CB  + 2L * 512 * 512;     // [30720,160]
constexpr long H_X0  = H_XIN + 2L * 30720 * 160;   // [30720,512]
constexpr long H_Q   = H_X0  + 2L * 30720 * 512;   // [1024,512]
constexpr long H_D0  = H_Q   + 2L * 1024 * 512;    // [1024,512]
constexpr long TOTALH= H_D0  + 2L * 1024 * 512;

__device__ __half g_hbuf[TOTALH];

// ======================= helpers ===========================================
__device__ __forceinline__ uint32_t smem_u32(const void* p)
{
    return (uint32_t)__cvta_generic_to_shared(p);
}

__device__ __forceinline__ void f16split(float x, __half& h, __half& l)
{
    h = __float2half_rn(x);
    l = __float2half_rn(x - __half2float(h));
}

__device__ __forceinline__ void mma_f16(float* c, const uint32_t* a, const uint32_t* b)
{
    asm volatile(
        "mma.sync.aligned.m16n8k16.row.col.f32.f16.f16.f32 "
        "{%0,%1,%2,%3}, {%4,%5,%6,%7}, {%8,%9}, {%0,%1,%2,%3};"
        : "+f"(c[0]), "+f"(c[1]), "+f"(c[2]), "+f"(c[3])
        : "r"(a[0]), "r"(a[1]), "r"(a[2]), "r"(a[3]), "r"(b[0]), "r"(b[1]));
}

__device__ __forceinline__ void ldm4(uint32_t& r0, uint32_t& r1, uint32_t& r2,
                                     uint32_t& r3, uint32_t addr)
{
    asm volatile("ldmatrix.sync.aligned.m8n8.x4.shared.b16 {%0,%1,%2,%3}, [%4];"
                 : "=r"(r0), "=r"(r1), "=r"(r2), "=r"(r3) : "r"(addr));
}

__device__ __forceinline__ void cp16(uint32_t dst, const void* src, int pred)
{
    asm volatile("cp.async.cg.shared.global [%0], [%1], 16, %2;"
                 :: "r"(dst), "l"(src), "r"(pred ? 16 : 0) : "memory");
}
__device__ __forceinline__ void cp_commit()
{
    asm volatile("cp.async.commit_group;" ::: "memory");
}

// 64B rows, chunk swizzle: byte = row*64 + ((ch ^ ((row>>1)&3)) * 16)
__device__ __forceinline__ uint32_t swz(int row, int ch)
{
    return (uint32_t)(row * 64 + ((ch ^ ((row >> 1) & 3)) << 4));
}

// ======================= GEMM ==============================================
// CTA tile (64*MTILES) x 128, BK=32 halves, 256 threads, 8 warps (4Mx2N),
// warp tile (16*MTILES) x 64. 3-stage cp.async pipeline, swizzled 64B rows.
// FUSEA=1: A operand is RAW f32 + BN stats; normalize+ReLU+split applied
// during A load (register prefetch), LUT of scale/shift in smem.

template<int MTILES, int FUSEA>
__global__ __launch_bounds__(256, 2)
void gemm_hh(const __half* __restrict__ A0, const __half* __restrict__ A1,
             const float* __restrict__ Araw,
             const float* __restrict__ asum, const float* __restrict__ assq,
             const float* __restrict__ agam, const float* __restrict__ abet,
             float invMa,
             const __half* __restrict__ B0, const __half* __restrict__ B1,
             const float* __restrict__ bias, float* __restrict__ Cf,
             __half* __restrict__ C0, __half* __restrict__ C1,
             float* __restrict__ gsum, float* __restrict__ gssq,
             int M, int N, int Kp, int perm)
{
    constexpr int AROWS   = 64 * MTILES;
    constexpr int OFF_A1_ = AROWS * 64;
    constexpr int OFF_B0_ = 2 * AROWS * 64;
    constexpr int OFF_B1_ = OFF_B0_ + 128 * 64;
    constexpr int STG     = OFF_B0_ + 2 * 128 * 64;
    constexpr int LUTB    = FUSEA ? 4096 : 0;

    extern __shared__ char dsm[];
    const uint32_t dynb = smem_u32(dsm);
    const uint32_t base = (dynb + 1023u) & ~1023u;
    char* smg = dsm + (base - dynb);

    const int tid  = threadIdx.x;
    const int wid  = tid >> 5;
    const int lane = tid & 31;
    const int wm   = (wid & 3) * (16 * MTILES);
    const int wn   = (wid >> 2) * 64;
    const int g    = lane >> 2;
    const int t    = lane & 3;
    const int m0   = blockIdx.y * AROWS;
    const int n0   = blockIdx.x * 128;

    const int nk = Kp >> 5;

    float* s_sc = (float*)smg;          // [512] (FUSEA only)
    float* s_sh = s_sc + 512;           // [512]
    if (FUSEA) {
        #pragma unroll
        for (int c = tid; c < 512; c += 256) {
            const float mn = asum[c] * invMa;
            const float vr = assq[c] * invMa - mn * mn;
            const float sc = rsqrtf(vr + EPSV) * agam[c];
            s_sc[c] = sc;
            s_sh[c] = abet[c] - mn * sc;
        }
        __syncthreads();
    }

    // B-only cp.async issue (and A too when !FUSEA)
    auto issue = [&](int k0, uint32_t stg) {
        if (!FUSEA) {
            #pragma unroll
            for (int i = 0; i < MTILES; ++i) {
                const int slot = tid + i * 256;
                const int row = slot >> 2, ch = slot & 3;
                const int gm = m0 + row;
                const int ok = gm < M;
                const long off = (long)(ok ? gm : 0) * Kp + ch * 8 + k0;
                const uint32_t d = swz(row, ch);
                cp16(stg + 0       + d, A0 + off, ok);
                cp16(stg + OFF_A1_ + d, A1 + off, ok);
            }
        }
        #pragma unroll
        for (int i = 0; i < 2; ++i) {
            const int slot = tid + i * 256;
            const int row = slot >> 2, ch = slot & 3;
            const int gn = n0 + row;
            const int ok = gn < N;
            const long off = (long)(ok ? gn : 0) * Kp + ch * 8 + k0;
            const uint32_t d = swz(row, ch);
            cp16(stg + OFF_B0_ + d, B0 + off, ok);
            cp16(stg + OFF_B1_ + d, B1 + off, ok);
        }
        cp_commit();
    };

    // fused A: raw f32 register load (one chunk) / normalize+split store
    float4 areg[2 * MTILES];
    auto ldA = [&](int k0) {
        #pragma unroll
        for (int i = 0; i < 2 * MTILES; ++i) {
            const int slot = tid + i * 256;
            const int row = slot >> 3;
            const int fq  = slot & 7;
            const int gm  = m0 + row;
            if (gm < M)
                areg[i] = *(const float4*)&Araw[(long)gm * Kp + k0 + fq * 4];
            else
                areg[i] = make_float4(0.f, 0.f, 0.f, 0.f);
        }
    };
    auto stsA = [&](char* stg, int k0) {
        #pragma unroll
        for (int i = 0; i < 2 * MTILES; ++i) {
            const int slot = tid + i * 256;
            const int row = slot >> 3;
            const int fq  = slot & 7;
            const float x[4] = {areg[i].x, areg[i].y, areg[i].z, areg[i].w};
            uint32_t hw[2], lw[2];
            #pragma unroll
            for (int j = 0; j < 4; j += 2) {
                const int c0 = (k0 + fq * 4 + j)     & 511;
                const int c1 = (k0 + fq * 4 + j + 1) & 511;
                float y0 = fmaf(x[j],     s_sc[c0], s_sh[c0]); y0 = y0 > 0.f ? y0 : 0.f;
                float y1 = fmaf(x[j + 1], s_sc[c1], s_sh[c1]); y1 = y1 > 0.f ? y1 : 0.f;
                __half h0, l0, h1, l1;
                f16split(y0, h0, l0);
                f16split(y1, h1, l1);
                hw[j >> 1] = ((uint32_t)__half_as_ushort(h1) << 16) | __half_as_ushort(h0);
                lw[j >> 1] = ((uint32_t)__half_as_ushort(l1) << 16) | __half_as_ushort(l0);
            }
            const uint32_t d = swz(row, fq >> 1) + (fq & 1) * 8;
            *(uint2*)(stg + d)            = make_uint2(hw[0], hw[1]);
            *(uint2*)(stg + OFF_A1_ + d)  = make_uint2(lw[0], lw[1]);
        }
    };

    float acc[MTILES][8][4];
    #pragma unroll
    for (int a = 0; a < MTILES; a++)
        #pragma unroll
        for (int b = 0; b < 8; b++)
            #pragma unroll
            for (int c = 0; c < 4; c++) acc[a][b][c] = 0.f;

    // prologue
    if (FUSEA) ldA(0);
    issue(0, base + LUTB);
    if (nk > 1) issue(32, base + LUTB + STG);

    for (int it = 0; it < nk; ++it) {
        const uint32_t stg_u = base + LUTB + (uint32_t)(it % 3) * STG;
        char* stg_c = smg + LUTB + (it % 3) * STG;

        if (FUSEA) {
            stsA(stg_c, it << 5);                 // split chunk 'it' into smem
            if (it + 1 < nk) ldA((it + 1) << 5);  // prefetch next raw chunk
        }
        if (it + 2 < nk) {
            issue((it + 2) << 5, base + LUTB + (uint32_t)((it + 2) % 3) * STG);
            asm volatile("cp.async.wait_group 2;" ::: "memory");
        } else if (it + 1 < nk) {
            asm volatile("cp.async.wait_group 1;" ::: "memory");
        } else {
            asm volatile("cp.async.wait_group 0;" ::: "memory");
        }
        __syncthreads();

        #pragma unroll
        for (int ks = 0; ks < 2; ++ks) {
            uint32_t aH[MTILES][4], aL[MTILES][4];
            {
                const int arw = (lane & 15);
                const int cA  = ks * 2 + (lane >> 4);
                #pragma unroll
                for (int mt = 0; mt < MTILES; ++mt) {
                    const int row = wm + mt * 16 + arw;
                    const uint32_t ad = stg_u + swz(row, cA);
                    ldm4(aH[mt][0], aH[mt][1], aH[mt][2], aH[mt][3], ad + 0);
                    ldm4(aL[mt][0], aL[mt][1], aL[mt][2], aL[mt][3], ad + OFF_A1_);
                }
            }
            const int brw = (lane >> 4) * 8 + (lane & 7);
            const int cB  = ks * 2 + ((lane >> 3) & 1);
            #pragma unroll
            for (int p = 0; p < 4; ++p) {
                uint32_t bH[4], bL[4];
                const int row = wn + p * 16 + brw;
                const uint32_t bd = stg_u + swz(row, cB);
                ldm4(bH[0], bH[1], bH[2], bH[3], bd + OFF_B0_);
                ldm4(bL[0], bL[1], bL[2], bL[3], bd + OFF_B1_);
                #pragma unroll
                for (int sub = 0; sub < 2; ++sub) {
                    const int nt = 2 * p + sub;
                    uint32_t b_h[2] = {bH[sub * 2], bH[sub * 2 + 1]};
                    uint32_t b_l[2] = {bL[sub * 2], bL[sub * 2 + 1]};
                    #pragma unroll
                    for (int mt = 0; mt < MTILES; ++mt) {
                        mma_f16(acc[mt][nt], aH[mt], b_h);
                        mma_f16(acc[mt][nt], aH[mt], b_l);
                        mma_f16(acc[mt][nt], aL[mt], b_h);
                    }
                }
            }
        }
        __syncthreads();
    }

    // ---- epilogue: stores ----
    const bool neven = ((N & 1) == 0);
    #pragma unroll
    for (int mt = 0; mt < MTILES; ++mt) {
        #pragma unroll
        for (int half = 0; half < 2; ++half) {
            const int gm = m0 + wm + mt * 16 + g + half * 8;
            if (gm >= M) continue;
            const int orow = perm ? ((gm & 1023) * 30 + (gm >> 10)) : gm;
            #pragma unroll
            for (int nt = 0; nt < 8; ++nt) {
                const int col = n0 + wn + nt * 8 + t * 2;
                if (col >= N) continue;
                float v0 = acc[mt][nt][half * 2 + 0];
                float v1 = acc[mt][nt][half * 2 + 1];
                if (bias) {
                    v0 += bias[col];
                    if (col + 1 < N) v1 += bias[col + 1];
                }
                if (Cf) {
                    if (neven && col + 1 < N) {
                        *(float2*)&Cf[(long)orow * N + col] = make_float2(v0, v1);
                    } else {
                        Cf[(long)orow * N + col] = v0;
                        if (col + 1 < N) Cf[(long)orow * N + col + 1] = v1;
                    }
                }
                if (C0 && neven && col + 1 < N) {
                    __half h0, l0, h1, l1;
                    f16split(v0, h0, l0);
                    f16split(v1, h1, l1);
                    *(__half2*)&C0[(long)orow * N + col] = __halves2half2(h0, h1);
                    *(__half2*)&C1[(long)orow * N + col] = __halves2half2(l0, l1);
                }
            }
        }
    }

    // ---- fused BN stats (raw accumulators; bias null for these layers) ----
    if (gsum) {
        float* ssum = (float*)(smg + LUTB);   // stage area is dead now
        float* ssq2 = ssum + 128;
        if (tid < 256) ((float*)(smg + LUTB))[tid] = 0.0f;
        __syncthreads();
        #pragma unroll
        for (int nt = 0; nt < 8; ++nt) {
            #pragma unroll
            for (int j = 0; j < 2; ++j) {
                float s = 0.f, s2 = 0.f;
                #pragma unroll
                for (int mt = 0; mt < MTILES; ++mt) {
                    #pragma unroll
                    for (int half = 0; half < 2; ++half) {
                        const float v = acc[mt][nt][half * 2 + j];
                        s += v; s2 += v * v;
                    }
                }
                #pragma unroll
                for (int o = 16; o >= 4; o >>= 1) {
                    s  += __shfl_down_sync(0xffffffffu, s,  o);
                    s2 += __shfl_down_sync(0xffffffffu, s2, o);
                }
                if (g == 0) {
                    const int cl = wn + nt * 8 + t * 2 + j;
                    atomicAdd(&ssum[cl], s);
                    atomicAdd(&ssq2[cl], s2);
                }
            }
        }
        __syncthreads();
        if (tid < 128 && n0 + tid < N) {
            atomicAdd(&gsum[(n0 + tid) & 511], ssum[tid]);
            atomicAdd(&gssq[(n0 + tid) & 511], ssq2[tid]);
        }
    }
}

constexpr int DS20 = 3 * (2 * 128 * 64 + 2 * 128 * 64) + 1024;           // 99328
constexpr int DS21 = DS20 + 4096;                                        // 103424
constexpr int DS10 = 3 * (2 * 64 * 64 + 2 * 128 * 64) + 1024;            // 74752
constexpr int DS11 = DS10 + 4096;                                        // 78848

// ======================= single prep kernel ================================
__global__ void prep_all(const float* __restrict__ w_e1, const float* __restrict__ w_e2,
                         const float* __restrict__ w_e3, const float* __restrict__ w_d1,
                         const float* __restrict__ w_d2, const float* __restrict__ w_d3,
                         const float* __restrict__ W_in, const float* __restrict__ W_q,
                         const float* __restrict__ W_out, const float* __restrict__ cb,
                         const float* __restrict__ input,
                         __half* hb, float* cn, float* stats, float* loss, int* cnt)
{
    const int  job = blockIdx.y;
    const long tid0 = (long)blockIdx.x * blockDim.x + threadIdx.x;
    const long strd = (long)gridDim.x * blockDim.x;

    auto enc = [&](const float* w, __half* h0, __half* h1, int Kk, int Kp) {
        const int I = 512, Ke = I * Kk;
        const long n = 512L * Kp;
        for (long j = tid0; j < n; j += strd) {
            const int o  = (int)(j / Kp);
            const int kk = (int)(j % Kp);
            float x = 0.f;
            if (kk < Ke) x = w[(long)o * Ke + (long)(kk % I) * Kk + (kk / I)];
            __half h, l; f16split(x, h, l);
            h0[j] = h; h1[j] = l;
        }
    };
    auto dec = [&](const float* w, __half* h0, __half* h1, int Kk) {
        const int I = 512, O = 512;
        const long n = (long)Kk * O * I;
        for (long j = tid0; j < n; j += strd) {
            const int i  = (int)(j % I);
            const int nn = (int)(j / I);
            const int o  = nn % O;
            const int k  = nn / O;
            const float x = w[(long)i * O * Kk + (long)o * Kk + k];
            __half h, l; f16split(x, h, l);
            h0[j] = h; h1[j] = l;
        }
    };
    auto tr = [&](const float* in, __half* h0, __half* h1, int R, int C, int Kp) {
        const long n = (long)C * Kp;
        for (long j = tid0; j < n; j += strd) {
            const int c = (int)(j / Kp);
            const int r = (int)(j % Kp);
            const float x = (r < R) ? in[(long)r * C + c] : 0.f;
            __half h, l; f16split(x, h, l);
            h0[j] = h; h1[j] = l;
        }
    };

    switch (job) {
    case 0: enc(w_e1, hb + H_WE1, hb + H_WE1 + 512L * 2560, 5, 2560); break;
    case 1: enc(w_e2, hb + H_WE2, hb + H_WE2 + 512L * 1536, 3, 1536); break;
    case 2: enc(w_e3, hb + H_WE3, hb + H_WE3 + 512L * 1024, 2, 1024); break;
    case 3: dec(w_d1, hb + H_WD1, hb + H_WD1 + 1024L * 512, 2); break;
    case 4: dec(w_d2, hb + H_WD2, hb + H_WD2 + 1536L * 512, 3); break;
    case 5: dec(w_d3, hb + H_WD3, hb + H_WD3 + 2560L * 512, 5); break;
    case 6: tr(W_in,  hb + H_WIT, hb + H_WIT + 512L * 160, 135, 512, 160); break;
    case 7: tr(W_q,   hb + H_WQT, hb + H_WQT + 512L * 512, 512, 512, 512); break;
    case 8: tr(W_out, hb + H_WOT, hb + H_WOT + 135L * 512, 512, 135, 512); break;
    case 9: {
        __half* h0 = hb + H_CB; __half* h1 = h0 + 512L * 512;
        for (long j = tid0; j < 512L * 512; j += strd) {
            __half h, l; f16split(cb[j], h, l);
            h0[j] = h; h1[j] = l;
        }
        break;
    }
    case 10: {
        __half* h0 = hb + H_XIN; __half* h1 = h0 + 30720L * 160;
        const long n = 30720L * 160;
        for (long j = tid0; j < n; j += strd) {
            const long r = j / 160;
            const int  c = (int)(j % 160);
            const float x = (c < 135) ? input[r * 135 + c] : 0.f;
            __half h, l; f16split(x, h, l);
            h0[j] = h; h1[j] = l;
        }
        break;
    }
    case 11: {
        for (long j = tid0; j < 6L * 2 * 512; j += strd) stats[j] = 0.0f;
        for (long j = tid0; j < 512; j += strd) cnt[j] = 0;
        if (tid0 == 0) loss[0] = 0.0f;
        for (long k = tid0; k < 512; k += strd) {
            float s = 0.f;
            for (int d = 0; d < 512; ++d) {
                const float v = cb[k * 512 + d];
                s += v * v;
            }
            cn[k] = s;
        }
        break;
    }
    }
}

// ======================= vector quantization ================================
// argmin + split-f16 quantized copy + counts + loss. z-norm recomputed inline
// from raw z + BN stats (scale/shift per thread = per channel).
__global__ void vq_argmin(const float* __restrict__ scores, const float* __restrict__ cnorm,
                          const float* __restrict__ cb,
                          const __half* __restrict__ cb0, const __half* __restrict__ cb1,
                          const float* __restrict__ zr,
                          const float* __restrict__ zsum, const float* __restrict__ zssq,
                          const float* __restrict__ zg, const float* __restrict__ zb,
                          __half* __restrict__ qh, __half* __restrict__ ql,
                          int* __restrict__ counts, float* __restrict__ loss)
{
    const int n = blockIdx.x;
    const int k = threadIdx.x;
    const float d = cnorm[k] - 2.0f * scores[(long)n * 512 + k];
    __shared__ float sv[512];
    __shared__ int   si[512];
    sv[k] = d; si[k] = k;
    __syncthreads();
    for (int st = 256; st > 0; st >>= 1) {
        if (k < st) {
            const float ov = sv[k + st];
            const int   oi = si[k + st];
            if (ov < sv[k] || (ov == sv[k] && oi < si[k])) { sv[k] = ov; si[k] = oi; }
        }
        __syncthreads();
    }
    const int best = si[0];
    __syncthreads();

    qh[(long)n * 512 + k] = cb0[(long)best * 512 + k];
    ql[(long)n * 512 + k] = cb1[(long)best * 512 + k];

    // z_norm on the fly (stats over M=1024 rows)
    const float invM = 1.0f / 1024.0f;
    const float mn = zsum[k] * invM;
    const float vr = zssq[k] * invM - mn * mn;
    const float sc = rsqrtf(vr + EPSV) * zg[k];
    float zn = fmaf(zr[(long)n * 512 + k], sc, zb[k] - mn * sc);
    zn = zn > 0.f ? zn : 0.f;

    const float diff = cb[(long)best * 512 + k] - zn;
    sv[k] = diff * diff;
    __syncthreads();
    for (int st = 256; st > 0; st >>= 1) {
        if (k < st) sv[k] += sv[k + st];
        __syncthreads();
    }
    if (k == 0) {
        atomicAdd(&counts[best], 1);
        atomicAdd(loss, sv[0]);
    }
}

__global__ void finalize_k(const int* __restrict__ counts, const float* __restrict__ loss,
                           float* __restrict__ out, long outsize)
{
    const int k = threadIdx.x;
    const float p = (float)counts[k] * (1.0f / 1024.0f);
    __shared__ float sh[512];
    sh[k] = p * logf(p + 1e-10f);
    __syncthreads();
    for (int st = 256; st > 0; st >>= 1) {
        if (k < st) sh[k] += sh[k + st];
        __syncthreads();
    }
    if (k == 0) {
        const long R = 1024L * 30 * 135;
        if (outsize >= R + 2) {
            out[R]     = loss[0] * 1.25f / (1024.0f * 512.0f);
            out[R + 1] = expf(-sh[0]);
        }
    }
}

// ======================= host launch ========================================
static inline dim3 grid128(int M, int N) { return dim3((N + 127) / 128, (M + 127) / 128); }
static inline dim3 grid64(int M, int N)  { return dim3((N + 127) / 128, (M + 63) / 64); }

extern "C" void kernel_launch(void* const* d_in, const int* in_sizes, int n_in,
                              void* d_out, int out_size)
{
    (void)in_sizes; (void)n_in;
    float* buf = nullptr;
    __half* hb = nullptr;
    cudaGetSymbolAddress((void**)&buf, g_buf);
    cudaGetSymbolAddress((void**)&hb, g_hbuf);
    cudaFuncSetAttribute((const void*)gemm_hh<2,0>, cudaFuncAttributeMaxDynamicSharedMemorySize, DS20);
    cudaFuncSetAttribute((const void*)gemm_hh<2,1>, cudaFuncAttributeMaxDynamicSharedMemorySize, DS21);
    cudaFuncSetAttribute((const void*)gemm_hh<1,0>, cudaFuncAttributeMaxDynamicSharedMemorySize, DS10);
    cudaFuncSetAttribute((const void*)gemm_hh<1,1>, cudaFuncAttributeMaxDynamicSharedMemorySize, DS11);

    const float* input = (const float*)d_in[0];
    const float* W_in  = (const float*)d_in[1];
    const float* b_in  = (const float*)d_in[2];
    const float* w_e1  = (const float*)d_in[3];
    const float* g_e1  = (const float*)d_in[4];
    const float* b_e1  = (const float*)d_in[5];
    const float* w_e2  = (const float*)d_in[6];
    const float* g_e2  = (const float*)d_in[7];
    const float* b_e2  = (const float*)d_in[8];
    const float* w_e3  = (const float*)d_in[9];
    const float* g_e3  = (const float*)d_in[10];
    const float* b_e3  = (const float*)d_in[11];
    const float* cb    = (const float*)d_in[12];
    const float* W_q   = (const float*)d_in[13];
    const float* b_q   = (const float*)d_in[14];
    const float* w_d1  = (const float*)d_in[15];
    const float* g_d1  = (const float*)d_in[16];
    const float* b_d1  = (const float*)d_in[17];
    const float* w_d2  = (const float*)d_in[18];
    const float* g_d2  = (const float*)d_in[19];
    const float* b_d2  = (const float*)d_in[20];
    const float* w_d3  = (const float*)d_in[21];
    const float* g_d3  = (const float*)d_in[22];
    const float* b_d3  = (const float*)d_in[23];
    const float* W_out = (const float*)d_in[24];
    const float* b_out = (const float*)d_in[25];

    float* e1r  = buf + O_E1R;
    float* e2r  = buf + O_E2R;
    float* zr   = buf + O_ZR;
    float* d1r  = buf + O_D1R;
    float* d2r  = buf + O_D2R;
    float* d3r  = buf + O_D3R;
    float* sc   = buf + O_SC;
    float* cn   = buf + O_CN;
    float* stats= buf + O_STAT;
    float* loss = buf + O_LOSS;
    int*   cnt  = (int*)(buf + O_CNT);

    __half* we1_0 = hb + H_WE1; __half* we1_1 = we1_0 + 512L * 2560;
    __half* we2_0 = hb + H_WE2; __half* we2_1 = we2_0 + 512L * 1536;
    __half* we3_0 = hb + H_WE3; __half* we3_1 = we3_0 + 512L * 1024;
    __half* wd1_0 = hb + H_WD1; __half* wd1_1 = wd1_0 + 1024L * 512;
    __half* wd2_0 = hb + H_WD2; __half* wd2_1 = wd2_0 + 1536L * 512;
    __half* wd3_0 = hb + H_WD3; __half* wd3_1 = wd3_0 + 2560L * 512;
    __half* wit_0 = hb + H_WIT; __half* wit_1 = wit_0 + 512L * 160;
    __half* wqt_0 = hb + H_WQT; __half* wqt_1 = wqt_0 + 512L * 512;
    __half* wot_0 = hb + H_WOT; __half* wot_1 = wot_0 + 135L * 512;
    __half* cb_0  = hb + H_CB;  __half* cb_1  = cb_0  + 512L * 512;
    __half* xin_0 = hb + H_XIN; __half* xin_1 = xin_0 + 30720L * 160;
    __half* x0_0  = hb + H_X0;  __half* x0_1  = x0_0  + 30720L * 512;
    __half* q_0   = hb + H_Q;   __half* q_1   = q_0   + 1024L * 512;
    __half* d0_0  = hb + H_D0;  __half* d0_1  = d0_0  + 1024L * 512;

    float* out = (float*)d_out;

    // ---- prep: everything in ONE launch ----
    prep_all<<<dim3(160, 12), 256>>>(w_e1, w_e2, w_e3, w_d1, w_d2, w_d3,
                                     W_in, W_q, W_out, cb, input,
                                     hb, cn, stats, loss, cnt);

    float* st0 = stats;
    float* st1 = stats + 1024;
    float* st2 = stats + 2048;
    float* st3 = stats + 3072;
    float* st4 = stats + 4096;
    float* st5 = stats + 5120;

    // ---- input GEMM: K=135(pad160) -> 512, split-only out, perm ----
    gemm_hh<2,0><<<grid128(30720, 512), 256, DS20>>>(
        xin_0, xin_1, nullptr, nullptr, nullptr, nullptr, nullptr, 0.f,
        wit_0, wit_1, b_in, nullptr, x0_0, x0_1,
        nullptr, nullptr, 30720, 512, 160, 1);

    // ---- e1: split A, raw out + stats ----
    gemm_hh<2,0><<<grid128(6144, 512), 256, DS20>>>(
        x0_0, x0_1, nullptr, nullptr, nullptr, nullptr, nullptr, 0.f,
        we1_0, we1_1, nullptr, e1r, nullptr, nullptr,
        st0, st0 + 512, 6144, 512, 2560, 0);

    // ---- e2: A = BN(e1r) fused ----
    gemm_hh<1,1><<<grid64(2048, 512), 256, DS11>>>(
        nullptr, nullptr, e1r, st0, st0 + 512, g_e1, b_e1, 1.0f / 6144.0f,
        we2_0, we2_1, nullptr, e2r, nullptr, nullptr,
        st1, st1 + 512, 2048, 512, 1536, 0);

    // ---- z: A = BN(e2r) fused ----
    gemm_hh<1,1><<<grid64(1024, 512), 256, DS11>>>(
        nullptr, nullptr, e2r, st1, st1 + 512, g_e2, b_e2, 1.0f / 2048.0f,
        we3_0, we3_1, nullptr, zr, nullptr, nullptr,
        st2, st2 + 512, 1024, 512, 1024, 0);

    // ---- scores: A = BN(zr) fused, B = codebook ----
    gemm_hh<1,1><<<grid64(1024, 512), 256, DS11>>>(
        nullptr, nullptr, zr, st2, st2 + 512, g_e3, b_e3, 1.0f / 1024.0f,
        cb_0, cb_1, nullptr, sc, nullptr, nullptr,
        nullptr, nullptr, 1024, 512, 512, 0);

    vq_argmin<<<1024, 512>>>(sc, cn, cb, cb_0, cb_1,
                             zr, st2, st2 + 512, g_e3, b_e3,
                             q_0, q_1, cnt, loss);

    // ---- d0: split A = q ----
    gemm_hh<1,0><<<grid64(1024, 512), 256, DS10>>>(
        q_0, q_1, nullptr, nullptr, nullptr, nullptr, nullptr, 0.f,
        wqt_0, wqt_1, b_q, nullptr, d0_0, d0_1,
        nullptr, nullptr, 1024, 512, 512, 0);

    // ---- d1: split A = d0, raw out + stats ----
    gemm_hh<1,0><<<grid64(1024, 1024), 256, DS10>>>(
        d0_0, d0_1, nullptr, nullptr, nullptr, nullptr, nullptr, 0.f,
        wd1_0, wd1_1, nullptr, d1r, nullptr, nullptr,
        st3, st3 + 512, 1024, 1024, 512, 0);

    // ---- d2: A = BN(d1r) fused ----
    gemm_hh<2,1><<<grid128(2048, 1536), 256, DS21>>>(
        nullptr, nullptr, d1r, st3, st3 + 512, g_d1, b_d1, 1.0f / 2048.0f,
        wd2_0, wd2_1, nullptr, d2r, nullptr, nullptr,
        st4, st4 + 512, 2048, 1536, 512, 0);

    // ---- d3: A = BN(d2r) fused ----
    gemm_hh<2,1><<<grid128(6144, 2560), 256, DS21>>>(
        nullptr, nullptr, d2r, st4, st4 + 512, g_d2, b_d2, 1.0f / 6144.0f,
        wd3_0, wd3_1, nullptr, d3r, nullptr, nullptr,
        st5, st5 + 512, 6144, 2560, 512, 0);

    // ---- out: A = BN(d3r) fused -> recon ----
    gemm_hh<2,1><<<grid128(30720, 135), 256, DS21>>>(
        nullptr, nullptr, d3r, st5, st5 + 512, g_d3, b_d3, 1.0f / 30720.0f,
        wot_0, wot_1, b_out, out, nullptr, nullptr,
        nullptr, nullptr, 30720, 135, 512, 0);

    // ---- scalars ----
    finalize_k<<<1, 512>>>(cnt, loss, out, (long)out_size);
}

// round 13
// speedup vs baseline: 1.0041x; 1.0041x over previous
#include <cuda_runtime.h>
#include <cuda_fp16.h>
#include <math.h>
#include <stdint.h>

// ---------------------------------------------------------------------------
// VQ-VAE forward. T=30, B=1024, D_POSE=135, H=512, K_CODES=512.
// Row-major GEMMs C[M,N] = A[M,K] * B'[N,K]^T, mma.sync.m16n8k16 f16,
// 3xFP16 hi/lo split (err ~2^-24). 3-stage cp.async pipeline, 64B swizzled
// smem rows. BN stats fused into producer GEMM epilogues.
// R13: BN-normalize fused into consumer A-load ONLY for big-grid decoder
// layers (d2/d3/out, run as MT1 => >=384 CTAs, 2 CTAs/SM); encoder keeps
// the separate bn_norm2 pass. Inactive N-edge warps skip all MMA work.
// ---------------------------------------------------------------------------

#define EPSV 1e-5f

// ======================= fp32 scratch ======================================
constexpr long O_E1R = 0;                        // 6144 x 512 (raw, pre-BN)
constexpr long O_E2R = O_E1R + 6144L * 512;      // 2048 x 512
constexpr long O_ZR  = O_E2R + 2048L * 512;      // 1024 x 512
constexpr long O_D1R = O_ZR  + 1024L * 512;      // 1024 x 1024
constexpr long O_D2R = O_D1R + 1024L * 1024;     // 2048 x 1536
constexpr long O_D3R = O_D2R + 2048L * 1536;     // 6144 x 2560
constexpr long O_SC  = O_D3R + 6144L * 2560;     // 1024 x 512
constexpr long O_CN  = O_SC  + 1024L * 512;      // 512
constexpr long O_STAT= O_CN  + 512;              // 6 x 2 x 512
constexpr long O_LOSS= O_STAT+ 6L * 2 * 512;
constexpr long O_CNT = O_LOSS+ 512;
constexpr long TOTALF= O_CNT + 512;

__device__ float g_buf[TOTALF];

// ======================= f16 split scratch (hi then lo per buffer) =========
constexpr long H_WE1 = 0;                          // [512,2560]
constexpr long H_WE2 = H_WE1 + 2L * 512 * 2560;    // [512,1536]
constexpr long H_WE3 = H_WE2 + 2L * 512 * 1536;    // [512,1024]
constexpr long H_WD1 = H_WE3 + 2L * 512 * 1024;    // [1024,512]
constexpr long H_WD2 = H_WD1 + 2L * 1024 * 512;    // [1536,512]
constexpr long H_WD3 = H_WD2 + 2L * 1536 * 512;    // [2560,512]
constexpr long H_WIT = H_WD3 + 2L * 2560 * 512;    // [512,160]
constexpr long H_WQT = H_WIT + 2L * 512 * 160;     // [512,512]
constexpr long H_WOT = H_WQT + 2L * 512 * 512;     // [135,512]
constexpr long H_CB  = H_WOT + 2L * 135 * 512;     // [512,512]
constexpr long H_XIN = H_CB  + 2L * 512 * 512;     // [30720,160]
constexpr long H_X0  = H_XIN + 2L * 30720 * 160;   // [30720,512]
constexpr long H_E1  = H_X0  + 2L * 30720 * 512;   // [6144,512]
constexpr long H_E2  = H_E1  + 2L * 6144 * 512;    // [2048,512]
constexpr long H_Z   = H_E2  + 2L * 2048 * 512;    // [1024,512]
constexpr long H_Q   = H_Z   + 2L * 1024 * 512;    // [1024,512]
constexpr long H_D0  = H_Q   + 2L * 1024 * 512;    // [1024,512]
constexpr long TOTALH= H_D0  + 2L * 1024 * 512;

__device__ __half g_hbuf[TOTALH];

// ======================= helpers ===========================================
__device__ __forceinline__ uint32_t smem_u32(const void* p)
{
    return (uint32_t)__cvta_generic_to_shared(p);
}

__device__ __forceinline__ void f16split(float x, __half& h, __half& l)
{
    h = __float2half_rn(x);
    l = __float2half_rn(x - __half2float(h));
}

__device__ __forceinline__ void mma_f16(float* c, const uint32_t* a, const uint32_t* b)
{
    asm volatile(
        "mma.sync.aligned.m16n8k16.row.col.f32.f16.f16.f32 "
        "{%0,%1,%2,%3}, {%4,%5,%6,%7}, {%8,%9}, {%0,%1,%2,%3};"
        : "+f"(c[0]), "+f"(c[1]), "+f"(c[2]), "+f"(c[3])
        : "r"(a[0]), "r"(a[1]), "r"(a[2]), "r"(a[3]), "r"(b[0]), "r"(b[1]));
}

__device__ __forceinline__ void ldm4(uint32_t& r0, uint32_t& r1, uint32_t& r2,
                                     uint32_t& r3, uint32_t addr)
{
    asm volatile("ldmatrix.sync.aligned.m8n8.x4.shared.b16 {%0,%1,%2,%3}, [%4];"
                 : "=r"(r0), "=r"(r1), "=r"(r2), "=r"(r3) : "r"(addr));
}

__device__ __forceinline__ void cp16(uint32_t dst, const void* src, int pred)
{
    asm volatile("cp.async.cg.shared.global [%0], [%1], 16, %2;"
                 :: "r"(dst), "l"(src), "r"(pred ? 16 : 0) : "memory");
}
__device__ __forceinline__ void cp_commit()
{
    asm volatile("cp.async.commit_group;" ::: "memory");
}

// 64B rows, chunk swizzle: byte = row*64 + ((ch ^ ((row>>1)&3)) * 16)
__device__ __forceinline__ uint32_t swz(int row, int ch)
{
    return (uint32_t)(row * 64 + ((ch ^ ((row >> 1) & 3)) << 4));
}

// ======================= GEMM ==============================================
// CTA tile (64*MTILES) x 128, BK=32 halves, 256 threads, 8 warps (4Mx2N),
// warp tile (16*MTILES) x 64. 3-stage cp.async pipeline, swizzled 64B rows.
// FUSEA=1: A is RAW f32 + BN stats; normalize+ReLU+split during A load
// (register prefetch, scale/shift LUT in smem). Use only with grid >= ~300.
// Warps whose 64-col span starts beyond N skip all fragment/MMA work.

template<int MTILES, int FUSEA>
__global__ __launch_bounds__(256, (MTILES == 2 || FUSEA) ? 2 : 1)
void gemm_hh(const __half* __restrict__ A0, const __half* __restrict__ A1,
             const float* __restrict__ Araw,
             const float* __restrict__ asum, const float* __restrict__ assq,
             const float* __restrict__ agam, const float* __restrict__ abet,
             float invMa,
             const __half* __restrict__ B0, const __half* __restrict__ B1,
             const float* __restrict__ bias, float* __restrict__ Cf,
             __half* __restrict__ C0, __half* __restrict__ C1,
             float* __restrict__ gsum, float* __restrict__ gssq,
             int M, int N, int Kp, int perm)
{
    constexpr int AROWS   = 64 * MTILES;
    constexpr int OFF_A1_ = AROWS * 64;
    constexpr int OFF_B0_ = 2 * AROWS * 64;
    constexpr int OFF_B1_ = OFF_B0_ + 128 * 64;
    constexpr int STG     = OFF_B0_ + 2 * 128 * 64;
    constexpr int LUTB    = FUSEA ? 4096 : 0;

    extern __shared__ char dsm[];
    const uint32_t dynb = smem_u32(dsm);
    const uint32_t base = (dynb + 1023u) & ~1023u;
    char* smg = dsm + (base - dynb);

    const int tid  = threadIdx.x;
    const int wid  = tid >> 5;
    const int lane = tid & 31;
    const int wm   = (wid & 3) * (16 * MTILES);
    const int wn   = (wid >> 2) * 64;
    const int g    = lane >> 2;
    const int t    = lane & 3;
    const int m0   = blockIdx.y * AROWS;
    const int n0   = blockIdx.x * 128;
    const bool wactive = (n0 + wn) < N;      // whole warp-span out of range?

    const int nk = Kp >> 5;

    float* s_sc = (float*)smg;          // [512] (FUSEA only)
    float* s_sh = s_sc + 512;           // [512]
    if (FUSEA) {
        #pragma unroll
        for (int c = tid; c < 512; c += 256) {
            const float mn = asum[c] * invMa;
            const float vr = assq[c] * invMa - mn * mn;
            const float sc = rsqrtf(vr + EPSV) * agam[c];
            s_sc[c] = sc;
            s_sh[c] = abet[c] - mn * sc;
        }
        __syncthreads();
    }

    auto issue = [&](int k0, uint32_t stg) {
        if (!FUSEA) {
            #pragma unroll
            for (int i = 0; i < MTILES; ++i) {
                const int slot = tid + i * 256;
                const int row = slot >> 2, ch = slot & 3;
                const int gm = m0 + row;
                const int ok = gm < M;
                const long off = (long)(ok ? gm : 0) * Kp + ch * 8 + k0;
                const uint32_t d = swz(row, ch);
                cp16(stg + 0       + d, A0 + off, ok);
                cp16(stg + OFF_A1_ + d, A1 + off, ok);
            }
        }
        #pragma unroll
        for (int i = 0; i < 2; ++i) {
            const int slot = tid + i * 256;
            const int row = slot >> 2, ch = slot & 3;
            const int gn = n0 + row;
            const int ok = gn < N;
            const long off = (long)(ok ? gn : 0) * Kp + ch * 8 + k0;
            const uint32_t d = swz(row, ch);
            cp16(stg + OFF_B0_ + d, B0 + off, ok);
            cp16(stg + OFF_B1_ + d, B1 + off, ok);
        }
        cp_commit();
    };

    // fused A: raw f32 register prefetch / normalize+split store
    float4 areg[2 * MTILES];
    auto ldA = [&](int k0) {
        #pragma unroll
        for (int i = 0; i < 2 * MTILES; ++i) {
            const int slot = tid + i * 256;
            const int row = slot >> 3;
            const int fq  = slot & 7;
            const int gm  = m0 + row;
            if (gm < M)
                areg[i] = *(const float4*)&Araw[(long)gm * Kp + k0 + fq * 4];
            else
                areg[i] = make_float4(0.f, 0.f, 0.f, 0.f);
        }
    };
    auto stsA = [&](char* stg, int k0) {
        #pragma unroll
        for (int i = 0; i < 2 * MTILES; ++i) {
            const int slot = tid + i * 256;
            const int row = slot >> 3;
            const int fq  = slot & 7;
            const float x[4] = {areg[i].x, areg[i].y, areg[i].z, areg[i].w};
            uint32_t hw[2], lw[2];
            #pragma unroll
            for (int j = 0; j < 4; j += 2) {
                const int c0 = (k0 + fq * 4 + j)     & 511;
                const int c1 = (k0 + fq * 4 + j + 1) & 511;
                float y0 = fmaf(x[j],     s_sc[c0], s_sh[c0]); y0 = y0 > 0.f ? y0 : 0.f;
                float y1 = fmaf(x[j + 1], s_sc[c1], s_sh[c1]); y1 = y1 > 0.f ? y1 : 0.f;
                __half h0, l0, h1, l1;
                f16split(y0, h0, l0);
                f16split(y1, h1, l1);
                hw[j >> 1] = ((uint32_t)__half_as_ushort(h1) << 16) | __half_as_ushort(h0);
                lw[j >> 1] = ((uint32_t)__half_as_ushort(l1) << 16) | __half_as_ushort(l0);
            }
            const uint32_t d = swz(row, fq >> 1) + (fq & 1) * 8;
            *(uint2*)(stg + d)            = make_uint2(hw[0], hw[1]);
            *(uint2*)(stg + OFF_A1_ + d)  = make_uint2(lw[0], lw[1]);
        }
    };

    float acc[MTILES][8][4];
    #pragma unroll
    for (int a = 0; a < MTILES; a++)
        #pragma unroll
        for (int b = 0; b < 8; b++)
            #pragma unroll
            for (int c = 0; c < 4; c++) acc[a][b][c] = 0.f;

    if (FUSEA) ldA(0);
    issue(0, base + LUTB);
    if (nk > 1) issue(32, base + LUTB + STG);

    for (int it = 0; it < nk; ++it) {
        const uint32_t stg_u = base + LUTB + (uint32_t)(it % 3) * STG;
        char* stg_c = smg + LUTB + (it % 3) * STG;

        if (FUSEA) {
            stsA(stg_c, it << 5);
            if (it + 1 < nk) ldA((it + 1) << 5);
        }
        if (it + 2 < nk) {
            issue((it + 2) << 5, base + LUTB + (uint32_t)((it + 2) % 3) * STG);
            asm volatile("cp.async.wait_group 2;" ::: "memory");
        } else if (it + 1 < nk) {
            asm volatile("cp.async.wait_group 1;" ::: "memory");
        } else {
            asm volatile("cp.async.wait_group 0;" ::: "memory");
        }
        __syncthreads();

        if (wactive) {
            #pragma unroll
            for (int ks = 0; ks < 2; ++ks) {
                uint32_t aH[MTILES][4], aL[MTILES][4];
                {
                    const int arw = (lane & 15);
                    const int cA  = ks * 2 + (lane >> 4);
                    #pragma unroll
                    for (int mt = 0; mt < MTILES; ++mt) {
                        const int row = wm + mt * 16 + arw;
                        const uint32_t ad = stg_u + swz(row, cA);
                        ldm4(aH[mt][0], aH[mt][1], aH[mt][2], aH[mt][3], ad + 0);
                        ldm4(aL[mt][0], aL[mt][1], aL[mt][2], aL[mt][3], ad + OFF_A1_);
                    }
                }
                const int brw = (lane >> 4) * 8 + (lane & 7);
                const int cB  = ks * 2 + ((lane >> 3) & 1);
                #pragma unroll
                for (int p = 0; p < 4; ++p) {
                    uint32_t bH[4], bL[4];
                    const int row = wn + p * 16 + brw;
                    const uint32_t bd = stg_u + swz(row, cB);
                    ldm4(bH[0], bH[1], bH[2], bH[3], bd + OFF_B0_);
                    ldm4(bL[0], bL[1], bL[2], bL[3], bd + OFF_B1_);
                    #pragma unroll
                    for (int sub = 0; sub < 2; ++sub) {
                        const int nt = 2 * p + sub;
                        uint32_t b_h[2] = {bH[sub * 2], bH[sub * 2 + 1]};
                        uint32_t b_l[2] = {bL[sub * 2], bL[sub * 2 + 1]};
                        #pragma unroll
                        for (int mt = 0; mt < MTILES; ++mt) {
                            mma_f16(acc[mt][nt], aH[mt], b_h);
                            mma_f16(acc[mt][nt], aH[mt], b_l);
                            mma_f16(acc[mt][nt], aL[mt], b_h);
                        }
                    }
                }
            }
        }
        __syncthreads();
    }

    // ---- epilogue: stores ----
    const bool neven = ((N & 1) == 0);
    if (wactive) {
        #pragma unroll
        for (int mt = 0; mt < MTILES; ++mt) {
            #pragma unroll
            for (int half = 0; half < 2; ++half) {
                const int gm = m0 + wm + mt * 16 + g + half * 8;
                if (gm >= M) continue;
                const int orow = perm ? ((gm & 1023) * 30 + (gm >> 10)) : gm;
                #pragma unroll
                for (int nt = 0; nt < 8; ++nt) {
                    const int col = n0 + wn + nt * 8 + t * 2;
                    if (col >= N) continue;
                    float v0 = acc[mt][nt][half * 2 + 0];
                    float v1 = acc[mt][nt][half * 2 + 1];
                    if (bias) {
                        v0 += bias[col];
                        if (col + 1 < N) v1 += bias[col + 1];
                    }
                    if (Cf) {
                        if (neven && col + 1 < N) {
                            *(float2*)&Cf[(long)orow * N + col] = make_float2(v0, v1);
                        } else {
                            Cf[(long)orow * N + col] = v0;
                            if (col + 1 < N) Cf[(long)orow * N + col + 1] = v1;
                        }
                    }
                    if (C0 && neven && col + 1 < N) {
                        __half h0, l0, h1, l1;
                        f16split(v0, h0, l0);
                        f16split(v1, h1, l1);
                        *(__half2*)&C0[(long)orow * N + col] = __halves2half2(h0, h1);
                        *(__half2*)&C1[(long)orow * N + col] = __halves2half2(l0, l1);
                    }
                }
            }
        }
    }

    // ---- fused BN stats ----
    if (gsum) {
        float* ssum = (float*)(smg + LUTB);
        float* ssq2 = ssum + 128;
        if (tid < 256) ((float*)(smg + LUTB))[tid] = 0.0f;
        __syncthreads();
        if (wactive) {
            #pragma unroll
            for (int nt = 0; nt < 8; ++nt) {
                #pragma unroll
                for (int j = 0; j < 2; ++j) {
                    float s = 0.f, s2 = 0.f;
                    #pragma unroll
                    for (int mt = 0; mt < MTILES; ++mt) {
                        #pragma unroll
                        for (int half = 0; half < 2; ++half) {
                            const float v = acc[mt][nt][half * 2 + j];
                            s += v; s2 += v * v;
                        }
                    }
                    #pragma unroll
                    for (int o = 16; o >= 4; o >>= 1) {
                        s  += __shfl_down_sync(0xffffffffu, s,  o);
                        s2 += __shfl_down_sync(0xffffffffu, s2, o);
                    }
                    if (g == 0) {
                        const int cl = wn + nt * 8 + t * 2 + j;
                        atomicAdd(&ssum[cl], s);
                        atomicAdd(&ssq2[cl], s2);
                    }
                }
            }
        }
        __syncthreads();
        if (tid < 128 && n0 + tid < N) {
            atomicAdd(&gsum[(n0 + tid) & 511], ssum[tid]);
            atomicAdd(&gssq[(n0 + tid) & 511], ssq2[tid]);
        }
    }
}

constexpr int DS20 = 3 * (2 * 128 * 64 + 2 * 128 * 64) + 1024;           // 99328
constexpr int DS10 = 3 * (2 * 64 * 64 + 2 * 128 * 64) + 1024;            // 74752
constexpr int DS11 = DS10 + 4096;                                        // 78848

// ======================= single prep kernel ================================
__global__ void prep_all(const float* __restrict__ w_e1, const float* __restrict__ w_e2,
                         const float* __restrict__ w_e3, const float* __restrict__ w_d1,
                         const float* __restrict__ w_d2, const float* __restrict__ w_d3,
                         const float* __restrict__ W_in, const float* __restrict__ W_q,
                         const float* __restrict__ W_out, const float* __restrict__ cb,
                         const float* __restrict__ input,
                         __half* hb, float* cn, float* stats, float* loss, int* cnt)
{
    const int  job = blockIdx.y;
    const long tid0 = (long)blockIdx.x * blockDim.x + threadIdx.x;
    const long strd = (long)gridDim.x * blockDim.x;

    auto enc = [&](const float* w, __half* h0, __half* h1, int Kk, int Kp) {
        const int I = 512, Ke = I * Kk;
        const long n = 512L * Kp;
        for (long j = tid0; j < n; j += strd) {
            const int o  = (int)(j / Kp);
            const int kk = (int)(j % Kp);
            float x = 0.f;
            if (kk < Ke) x = w[(long)o * Ke + (long)(kk % I) * Kk + (kk / I)];
            __half h, l; f16split(x, h, l);
            h0[j] = h; h1[j] = l;
        }
    };
    auto dec = [&](const float* w, __half* h0, __half* h1, int Kk) {
        const int I = 512, O = 512;
        const long n = (long)Kk * O * I;
        for (long j = tid0; j < n; j += strd) {
            const int i  = (int)(j % I);
            const int nn = (int)(j / I);
            const int o  = nn % O;
            const int k  = nn / O;
            const float x = w[(long)i * O * Kk + (long)o * Kk + k];
            __half h, l; f16split(x, h, l);
            h0[j] = h; h1[j] = l;
        }
    };
    auto tr = [&](const float* in, __half* h0, __half* h1, int R, int C, int Kp) {
        const long n = (long)C * Kp;
        for (long j = tid0; j < n; j += strd) {
            const int c = (int)(j / Kp);
            const int r = (int)(j % Kp);
            const float x = (r < R) ? in[(long)r * C + c] : 0.f;
            __half h, l; f16split(x, h, l);
            h0[j] = h; h1[j] = l;
        }
    };

    switch (job) {
    case 0: enc(w_e1, hb + H_WE1, hb + H_WE1 + 512L * 2560, 5, 2560); break;
    case 1: enc(w_e2, hb + H_WE2, hb + H_WE2 + 512L * 1536, 3, 1536); break;
    case 2: enc(w_e3, hb + H_WE3, hb + H_WE3 + 512L * 1024, 2, 1024); break;
    case 3: dec(w_d1, hb + H_WD1, hb + H_WD1 + 1024L * 512, 2); break;
    case 4: dec(w_d2, hb + H_WD2, hb + H_WD2 + 1536L * 512, 3); break;
    case 5: dec(w_d3, hb + H_WD3, hb + H_WD3 + 2560L * 512, 5); break;
    case 6: tr(W_in,  hb + H_WIT, hb + H_WIT + 512L * 160, 135, 512, 160); break;
    case 7: tr(W_q,   hb + H_WQT, hb + H_WQT + 512L * 512, 512, 512, 512); break;
    case 8: tr(W_out, hb + H_WOT, hb + H_WOT + 135L * 512, 512, 135, 512); break;
    case 9: {
        __half* h0 = hb + H_CB; __half* h1 = h0 + 512L * 512;
        for (long j = tid0; j < 512L * 512; j += strd) {
            __half h, l; f16split(cb[j], h, l);
            h0[j] = h; h1[j] = l;
        }
        break;
    }
    case 10: {
        __half* h0 = hb + H_XIN; __half* h1 = h0 + 30720L * 160;
        const long n = 30720L * 160;
        for (long j = tid0; j < n; j += strd) {
            const long r = j / 160;
            const int  c = (int)(j % 160);
            const float x = (c < 135) ? input[r * 135 + c] : 0.f;
            __half h, l; f16split(x, h, l);
            h0[j] = h; h1[j] = l;
        }
        break;
    }
    case 11: {
        for (long j = tid0; j < 6L * 2 * 512; j += strd) stats[j] = 0.0f;
        for (long j = tid0; j < 512; j += strd) cnt[j] = 0;
        if (tid0 == 0) loss[0] = 0.0f;
        for (long k = tid0; k < 512; k += strd) {
            float s = 0.f;
            for (int d = 0; d < 512; ++d) {
                const float v = cb[k * 512 + d];
                s += v * v;
            }
            cn[k] = s;
        }
        break;
    }
    }
}

// ======================= BN normalize (+ReLU), 4-wide, smem LUT =============
__global__ void bn_norm2(const float* __restrict__ X,
                         const float* __restrict__ gamma, const float* __restrict__ beta,
                         const float* __restrict__ gsum, const float* __restrict__ gssq,
                         int M, __half* __restrict__ h0, __half* __restrict__ h1)
{
    __shared__ float s_scale[512], s_shift[512];
    const float invM = 1.0f / (float)M;
    for (int c = threadIdx.x; c < 512; c += blockDim.x) {
        const float mn = gsum[c] * invM;
        const float vr = gssq[c] * invM - mn * mn;
        const float sc = rsqrtf(vr + EPSV) * gamma[c];
        s_scale[c] = sc;
        s_shift[c] = beta[c] - mn * sc;
    }
    __syncthreads();

    const int total4 = (M * 512) >> 2;
    for (int i4 = blockIdx.x * blockDim.x + threadIdx.x; i4 < total4;
         i4 += gridDim.x * blockDim.x) {
        const long i = (long)i4 << 2;
        const int c0 = (int)(i & 511);
        const float4 x = *(const float4*)&X[i];
        const float v[4] = {x.x, x.y, x.z, x.w};
        __half hh[4], ll[4];
        #pragma unroll
        for (int j = 0; j < 4; ++j) {
            float y = fmaf(v[j], s_scale[c0 + j], s_shift[c0 + j]);
            y = y > 0.0f ? y : 0.0f;
            f16split(y, hh[j], ll[j]);
        }
        *(__half2*)&h0[i]     = __halves2half2(hh[0], hh[1]);
        *(__half2*)&h0[i + 2] = __halves2half2(hh[2], hh[3]);
        *(__half2*)&h1[i]     = __halves2half2(ll[0], ll[1]);
        *(__half2*)&h1[i + 2] = __halves2half2(ll[2], ll[3]);
    }
}

// ======================= vector quantization ================================
__global__ void vq_argmin(const float* __restrict__ scores, const float* __restrict__ cnorm,
                          const float* __restrict__ cb,
                          const __half* __restrict__ cb0, const __half* __restrict__ cb1,
                          const float* __restrict__ zr,
                          const float* __restrict__ zsum, const float* __restrict__ zssq,
                          const float* __restrict__ zg, const float* __restrict__ zb,
                          __half* __restrict__ qh, __half* __restrict__ ql,
                          int* __restrict__ counts, float* __restrict__ loss)
{
    const int n = blockIdx.x;
    const int k = threadIdx.x;
    const float d = cnorm[k] - 2.0f * scores[(long)n * 512 + k];
    __shared__ float sv[512];
    __shared__ int   si[512];
    sv[k] = d; si[k] = k;
    __syncthreads();
    for (int st = 256; st > 0; st >>= 1) {
        if (k < st) {
            const float ov = sv[k + st];
            const int   oi = si[k + st];
            if (ov < sv[k] || (ov == sv[k] && oi < si[k])) { sv[k] = ov; si[k] = oi; }
        }
        __syncthreads();
    }
    const int best = si[0];
    __syncthreads();

    qh[(long)n * 512 + k] = cb0[(long)best * 512 + k];
    ql[(long)n * 512 + k] = cb1[(long)best * 512 + k];

    const float invM = 1.0f / 1024.0f;
    const float mn = zsum[k] * invM;
    const float vr = zssq[k] * invM - mn * mn;
    const float sc = rsqrtf(vr + EPSV) * zg[k];
    float zn = fmaf(zr[(long)n * 512 + k], sc, zb[k] - mn * sc);
    zn = zn > 0.f ? zn : 0.f;

    const float diff = cb[(long)best * 512 + k] - zn;
    sv[k] = diff * diff;
    __syncthreads();
    for (int st = 256; st > 0; st >>= 1) {
        if (k < st) sv[k] += sv[k + st];
        __syncthreads();
    }
    if (k == 0) {
        atomicAdd(&counts[best], 1);
        atomicAdd(loss, sv[0]);
    }
}

__global__ void finalize_k(const int* __restrict__ counts, const float* __restrict__ loss,
                           float* __restrict__ out, long outsize)
{
    const int k = threadIdx.x;
    const float p = (float)counts[k] * (1.0f / 1024.0f);
    __shared__ float sh[512];
    sh[k] = p * logf(p + 1e-10f);
    __syncthreads();
    for (int st = 256; st > 0; st >>= 1) {
        if (k < st) sh[k] += sh[k + st];
        __syncthreads();
    }
    if (k == 0) {
        const long R = 1024L * 30 * 135;
        if (outsize >= R + 2) {
            out[R]     = loss[0] * 1.25f / (1024.0f * 512.0f);
            out[R + 1] = expf(-sh[0]);
        }
    }
}

// ======================= host launch ========================================
static inline dim3 grid128(int M, int N) { return dim3((N + 127) / 128, (M + 127) / 128); }
static inline dim3 grid64(int M, int N)  { return dim3((N + 127) / 128, (M + 63) / 64); }

extern "C" void kernel_launch(void* const* d_in, const int* in_sizes, int n_in,
                              void* d_out, int out_size)
{
    (void)in_sizes; (void)n_in;
    float* buf = nullptr;
    __half* hb = nullptr;
    cudaGetSymbolAddress((void**)&buf, g_buf);
    cudaGetSymbolAddress((void**)&hb, g_hbuf);
    cudaFuncSetAttribute((const void*)gemm_hh<2,0>, cudaFuncAttributeMaxDynamicSharedMemorySize, DS20);
    cudaFuncSetAttribute((const void*)gemm_hh<1,0>, cudaFuncAttributeMaxDynamicSharedMemorySize, DS10);
    cudaFuncSetAttribute((const void*)gemm_hh<1,1>, cudaFuncAttributeMaxDynamicSharedMemorySize, DS11);

    const float* input = (const float*)d_in[0];
    const float* W_in  = (const float*)d_in[1];
    const float* b_in  = (const float*)d_in[2];
    const float* w_e1  = (const float*)d_in[3];
    const float* g_e1  = (const float*)d_in[4];
    const float* b_e1  = (const float*)d_in[5];
    const float* w_e2  = (const float*)d_in[6];
    const float* g_e2  = (const float*)d_in[7];
    const float* b_e2  = (const float*)d_in[8];
    const float* w_e3  = (const float*)d_in[9];
    const float* g_e3  = (const float*)d_in[10];
    const float* b_e3  = (const float*)d_in[11];
    const float* cb    = (const float*)d_in[12];
    const float* W_q   = (const float*)d_in[13];
    const float* b_q   = (const float*)d_in[14];
    const float* w_d1  = (const float*)d_in[15];
    const float* g_d1  = (const float*)d_in[16];
    const float* b_d1  = (const float*)d_in[17];
    const float* w_d2  = (const float*)d_in[18];
    const float* g_d2  = (const float*)d_in[19];
    const float* b_d2  = (const float*)d_in[20];
    const float* w_d3  = (const float*)d_in[21];
    const float* g_d3  = (const float*)d_in[22];
    const float* b_d3  = (const float*)d_in[23];
    const float* W_out = (const float*)d_in[24];
    const float* b_out = (const float*)d_in[25];

    float* e1r  = buf + O_E1R;
    float* e2r  = buf + O_E2R;
    float* zr   = buf + O_ZR;
    float* d1r  = buf + O_D1R;
    float* d2r  = buf + O_D2R;
    float* d3r  = buf + O_D3R;
    float* sc   = buf + O_SC;
    float* cn   = buf + O_CN;
    float* stats= buf + O_STAT;
    float* loss = buf + O_LOSS;
    int*   cnt  = (int*)(buf + O_CNT);

    __half* we1_0 = hb + H_WE1; __half* we1_1 = we1_0 + 512L * 2560;
    __half* we2_0 = hb + H_WE2; __half* we2_1 = we2_0 + 512L * 1536;
    __half* we3_0 = hb + H_WE3; __half* we3_1 = we3_0 + 512L * 1024;
    __half* wd1_0 = hb + H_WD1; __half* wd1_1 = wd1_0 + 1024L * 512;
    __half* wd2_0 = hb + H_WD2; __half* wd2_1 = wd2_0 + 1536L * 512;
    __half* wd3_0 = hb + H_WD3; __half* wd3_1 = wd3_0 + 2560L * 512;
    __half* wit_0 = hb + H_WIT; __half* wit_1 = wit_0 + 512L * 160;
    __half* wqt_0 = hb + H_WQT; __half* wqt_1 = wqt_0 + 512L * 512;
    __half* wot_0 = hb + H_WOT; __half* wot_1 = wot_0 + 135L * 512;
    __half* cb_0  = hb + H_CB;  __half* cb_1  = cb_0  + 512L * 512;
    __half* xin_0 = hb + H_XIN; __half* xin_1 = xin_0 + 30720L * 160;
    __half* x0_0  = hb + H_X0;  __half* x0_1  = x0_0  + 30720L * 512;
    __half* e1_0  = hb + H_E1;  __half* e1_1  = e1_0  + 6144L * 512;
    __half* e2_0  = hb + H_E2;  __half* e2_1  = e2_0  + 2048L * 512;
    __half* z_0   = hb + H_Z;   __half* z_1   = z_0   + 1024L * 512;
    __half* q_0   = hb + H_Q;   __half* q_1   = q_0   + 1024L * 512;
    __half* d0_0  = hb + H_D0;  __half* d0_1  = d0_0  + 1024L * 512;

    float* out = (float*)d_out;

    // ---- prep: everything in ONE launch ----
    prep_all<<<dim3(160, 12), 256>>>(w_e1, w_e2, w_e3, w_d1, w_d2, w_d3,
                                     W_in, W_q, W_out, cb, input,
                                     hb, cn, stats, loss, cnt);

    float* st0 = stats;
    float* st1 = stats + 1024;
    float* st2 = stats + 2048;
    float* st3 = stats + 3072;
    float* st4 = stats + 4096;
    float* st5 = stats + 5120;

    // ---- input GEMM: K=135(pad160) -> 512, split-only out, perm ----
    gemm_hh<2,0><<<grid128(30720, 512), 256, DS20>>>(
        xin_0, xin_1, nullptr, nullptr, nullptr, nullptr, nullptr, 0.f,
        wit_0, wit_1, b_in, nullptr, x0_0, x0_1,
        nullptr, nullptr, 30720, 512, 160, 1);

    // ---- encoder: unfused GEMMs + bn_norm2 (small grids) ----
    gemm_hh<2,0><<<grid128(6144, 512), 256, DS20>>>(
        x0_0, x0_1, nullptr, nullptr, nullptr, nullptr, nullptr, 0.f,
        we1_0, we1_1, nullptr, e1r, nullptr, nullptr,
        st0, st0 + 512, 6144, 512, 2560, 0);
    bn_norm2<<<2048, 256>>>(e1r, g_e1, b_e1, st0, st0 + 512, 6144, e1_0, e1_1);

    gemm_hh<1,0><<<grid64(2048, 512), 256, DS10>>>(
        e1_0, e1_1, nullptr, nullptr, nullptr, nullptr, nullptr, 0.f,
        we2_0, we2_1, nullptr, e2r, nullptr, nullptr,
        st1, st1 + 512, 2048, 512, 1536, 0);
    bn_norm2<<<1024, 256>>>(e2r, g_e2, b_e2, st1, st1 + 512, 2048, e2_0, e2_1);

    gemm_hh<1,0><<<grid64(1024, 512), 256, DS10>>>(
        e2_0, e2_1, nullptr, nullptr, nullptr, nullptr, nullptr, 0.f,
        we3_0, we3_1, nullptr, zr, nullptr, nullptr,
        st2, st2 + 512, 1024, 512, 1024, 0);
    bn_norm2<<<512, 256>>>(zr, g_e3, b_e3, st2, st2 + 512, 1024, z_0, z_1);

    // ---- vector quantization ----
    gemm_hh<1,0><<<grid64(1024, 512), 256, DS10>>>(
        z_0, z_1, nullptr, nullptr, nullptr, nullptr, nullptr, 0.f,
        cb_0, cb_1, nullptr, sc, nullptr, nullptr,
        nullptr, nullptr, 1024, 512, 512, 0);
    vq_argmin<<<1024, 512>>>(sc, cn, cb, cb_0, cb_1,
                             zr, st2, st2 + 512, g_e3, b_e3,
                             q_0, q_1, cnt, loss);

    // ---- decoder ----
    gemm_hh<1,0><<<grid64(1024, 512), 256, DS10>>>(
        q_0, q_1, nullptr, nullptr, nullptr, nullptr, nullptr, 0.f,
        wqt_0, wqt_1, b_q, nullptr, d0_0, d0_1,
        nullptr, nullptr, 1024, 512, 512, 0);

    gemm_hh<1,0><<<grid64(1024, 1024), 256, DS10>>>(
        d0_0, d0_1, nullptr, nullptr, nullptr, nullptr, nullptr, 0.f,
        wd1_0, wd1_1, nullptr, d1r, nullptr, nullptr,
        st3, st3 + 512, 1024, 1024, 512, 0);

    // d2: A = BN(d1r) fused, MT1 geometry -> grid 384
    gemm_hh<1,1><<<grid64(2048, 1536), 256, DS11>>>(
        nullptr, nullptr, d1r, st3, st3 + 512, g_d1, b_d1, 1.0f / 2048.0f,
        wd2_0, wd2_1, nullptr, d2r, nullptr, nullptr,
        st4, st4 + 512, 2048, 1536, 512, 0);

    // d3: A = BN(d2r) fused, grid 1920
    gemm_hh<1,1><<<grid64(6144, 2560), 256, DS11>>>(
        nullptr, nullptr, d2r, st4, st4 + 512, g_d2, b_d2, 1.0f / 6144.0f,
        wd3_0, wd3_1, nullptr, d3r, nullptr, nullptr,
        st5, st5 + 512, 6144, 2560, 512, 0);

    // out: A = BN(d3r) fused, grid 960 -> recon
    gemm_hh<1,1><<<grid64(30720, 135), 256, DS11>>>(
        nullptr, nullptr, d3r, st5, st5 + 512, g_d3, b_d3, 1.0f / 30720.0f,
        wot_0, wot_1, b_out, out, nullptr, nullptr,
        nullptr, nullptr, 30720, 135, 512, 0);

    // ---- scalars ----
    finalize_k<<<1, 512>>>(cnt, loss, out, (long)out_size);
}

// round 14
// speedup vs baseline: 1.0318x; 1.0276x over previous
#include <cuda_runtime.h>
#include <cuda_fp16.h>
#include <math.h>
#include <stdint.h>

// ---------------------------------------------------------------------------
// VQ-VAE forward. T=30, B=1024, D_POSE=135, H=512, K_CODES=512.
// Row-major GEMMs C[M,N] = A[M,K] * B'[N,K]^T, mma.sync.m16n8k16 f16,
// 3xFP16 hi/lo split (err ~2^-24). All operands pre-split f16 in gmem;
// mainloop pure cp.async + ldmatrix + mma. 3-stage pipeline, 64B swizzled
// rows, 2 CTAs/SM on MT2. BN stats fused into producer epilogues; normalize
// as a separate vectorized pass (fusing it into GEMM A-load was measured
// slower twice — R12/R13). R14 = R11 + inactive-N-warp skip + lean VQ.
// ---------------------------------------------------------------------------

#define EPSV 1e-5f

// ======================= fp32 scratch ======================================
constexpr long O_E1R = 0;                        // 6144 x 512 (raw, pre-BN)
constexpr long O_E2R = O_E1R + 6144L * 512;      // 2048 x 512
constexpr long O_ZR  = O_E2R + 2048L * 512;      // 1024 x 512
constexpr long O_D1R = O_ZR  + 1024L * 512;      // 1024 x 1024
constexpr long O_D2R = O_D1R + 1024L * 1024;     // 2048 x 1536
constexpr long O_D3R = O_D2R + 2048L * 1536;     // 6144 x 2560
constexpr long O_SC  = O_D3R + 6144L * 2560;     // 1024 x 512
constexpr long O_CN  = O_SC  + 1024L * 512;      // 512
constexpr long O_STAT= O_CN  + 512;              // 6 x 2 x 512
constexpr long O_LOSS= O_STAT+ 6L * 2 * 512;
constexpr long O_CNT = O_LOSS+ 512;
constexpr long TOTALF= O_CNT + 512;

__device__ float g_buf[TOTALF];

// ======================= f16 split scratch (hi then lo per buffer) =========
constexpr long H_WE1 = 0;                          // [512,2560]
constexpr long H_WE2 = H_WE1 + 2L * 512 * 2560;    // [512,1536]
constexpr long H_WE3 = H_WE2 + 2L * 512 * 1536;    // [512,1024]
constexpr long H_WD1 = H_WE3 + 2L * 512 * 1024;    // [1024,512]
constexpr long H_WD2 = H_WD1 + 2L * 1024 * 512;    // [1536,512]
constexpr long H_WD3 = H_WD2 + 2L * 1536 * 512;    // [2560,512]
constexpr long H_WIT = H_WD3 + 2L * 2560 * 512;    // [512,160]
constexpr long H_WQT = H_WIT + 2L * 512 * 160;     // [512,512]
constexpr long H_WOT = H_WQT + 2L * 512 * 512;     // [135,512]
constexpr long H_CB  = H_WOT + 2L * 135 * 512;     // [512,512]
constexpr long H_XIN = H_CB  + 2L * 512 * 512;     // [30720,160]
constexpr long H_X0  = H_XIN + 2L * 30720 * 160;   // [30720,512]
constexpr long H_E1  = H_X0  + 2L * 30720 * 512;   // [6144,512]
constexpr long H_E2  = H_E1  + 2L * 6144 * 512;    // [2048,512]
constexpr long H_Z   = H_E2  + 2L * 2048 * 512;    // [1024,512]
constexpr long H_Q   = H_Z   + 2L * 1024 * 512;    // [1024,512]
constexpr long H_D0  = H_Q   + 2L * 1024 * 512;    // [1024,512]
constexpr long H_D1  = H_D0  + 2L * 1024 * 512;    // [1024,1024]
constexpr long H_D2  = H_D1  + 2L * 1024 * 1024;   // [2048,1536]
constexpr long H_D3  = H_D2  + 2L * 2048 * 1536;   // [30720,512]
constexpr long TOTALH= H_D3  + 2L * 30720 * 512;

__device__ __half g_hbuf[TOTALH];

// ======================= helpers ===========================================
__device__ __forceinline__ uint32_t smem_u32(const void* p)
{
    return (uint32_t)__cvta_generic_to_shared(p);
}

__device__ __forceinline__ void f16split(float x, __half& h, __half& l)
{
    h = __float2half_rn(x);
    l = __float2half_rn(x - __half2float(h));
}

__device__ __forceinline__ void mma_f16(float* c, const uint32_t* a, const uint32_t* b)
{
    asm volatile(
        "mma.sync.aligned.m16n8k16.row.col.f32.f16.f16.f32 "
        "{%0,%1,%2,%3}, {%4,%5,%6,%7}, {%8,%9}, {%0,%1,%2,%3};"
        : "+f"(c[0]), "+f"(c[1]), "+f"(c[2]), "+f"(c[3])
        : "r"(a[0]), "r"(a[1]), "r"(a[2]), "r"(a[3]), "r"(b[0]), "r"(b[1]));
}

__device__ __forceinline__ void ldm4(uint32_t& r0, uint32_t& r1, uint32_t& r2,
                                     uint32_t& r3, uint32_t addr)
{
    asm volatile("ldmatrix.sync.aligned.m8n8.x4.shared.b16 {%0,%1,%2,%3}, [%4];"
                 : "=r"(r0), "=r"(r1), "=r"(r2), "=r"(r3) : "r"(addr));
}

__device__ __forceinline__ void cp16(uint32_t dst, const void* src, int pred)
{
    asm volatile("cp.async.cg.shared.global [%0], [%1], 16, %2;"
                 :: "r"(dst), "l"(src), "r"(pred ? 16 : 0) : "memory");
}
__device__ __forceinline__ void cp_commit()
{
    asm volatile("cp.async.commit_group;" ::: "memory");
}

// 64B rows, chunk swizzle: byte = row*64 + ((ch ^ ((row>>1)&3)) * 16)
__device__ __forceinline__ uint32_t swz(int row, int ch)
{
    return (uint32_t)(row * 64 + ((ch ^ ((row >> 1) & 3)) << 4));
}

// ======================= GEMM ==============================================
// CTA tile (64*MTILES) x 128, BK=32 halves, 256 threads, 8 warps (4Mx2N),
// warp tile (16*MTILES) x 64. 3-stage cp.async pipeline, swizzled 64B rows.
// MTILES=2 register-capped for 2 CTAs/SM. Warps whose 64-col span starts
// beyond N skip all fragment/MMA/epilogue work (N=135 output GEMM).

template<int MTILES>
__global__ __launch_bounds__(256, (MTILES == 2) ? 2 : 1)
void gemm_hh(const __half* __restrict__ A0, const __half* __restrict__ A1,
             const __half* __restrict__ B0, const __half* __restrict__ B1,
             const float* __restrict__ bias, float* __restrict__ Cf,
             __half* __restrict__ C0, __half* __restrict__ C1,
             float* __restrict__ gsum, float* __restrict__ gssq,
             int M, int N, int Kp, int perm)
{
    constexpr int AROWS   = 64 * MTILES;
    constexpr int OFF_A1_ = AROWS * 64;
    constexpr int OFF_B0_ = 2 * AROWS * 64;
    constexpr int OFF_B1_ = OFF_B0_ + 128 * 64;
    constexpr int STG     = OFF_B0_ + 2 * 128 * 64;

    extern __shared__ char dsm[];
    const uint32_t dynb = smem_u32(dsm);
    const uint32_t base = (dynb + 1023u) & ~1023u;
    char* smg = dsm + (base - dynb);

    const int tid  = threadIdx.x;
    const int wid  = tid >> 5;
    const int lane = tid & 31;
    const int wm   = (wid & 3) * (16 * MTILES);
    const int wn   = (wid >> 2) * 64;
    const int g    = lane >> 2;
    const int t    = lane & 3;
    const int m0   = blockIdx.y * AROWS;
    const int n0   = blockIdx.x * 128;
    const bool wactive = (n0 + wn) < N;

    const int nk = Kp >> 5;

    auto issue = [&](int k0, uint32_t stg) {
        #pragma unroll
        for (int i = 0; i < MTILES; ++i) {
            const int slot = tid + i * 256;
            const int row = slot >> 2, ch = slot & 3;
            const int gm = m0 + row;
            const int ok = gm < M;
            const long off = (long)(ok ? gm : 0) * Kp + ch * 8 + k0;
            const uint32_t d = swz(row, ch);
            cp16(stg + 0       + d, A0 + off, ok);
            cp16(stg + OFF_A1_ + d, A1 + off, ok);
        }
        #pragma unroll
        for (int i = 0; i < 2; ++i) {
            const int slot = tid + i * 256;
            const int row = slot >> 2, ch = slot & 3;
            const int gn = n0 + row;
            const int ok = gn < N;
            const long off = (long)(ok ? gn : 0) * Kp + ch * 8 + k0;
            const uint32_t d = swz(row, ch);
            cp16(stg + OFF_B0_ + d, B0 + off, ok);
            cp16(stg + OFF_B1_ + d, B1 + off, ok);
        }
        cp_commit();
    };

    float acc[MTILES][8][4];
    #pragma unroll
    for (int a = 0; a < MTILES; a++)
        #pragma unroll
        for (int b = 0; b < 8; b++)
            #pragma unroll
            for (int c = 0; c < 4; c++) acc[a][b][c] = 0.f;

    issue(0, base);
    if (nk > 1) issue(32, base + STG);

    for (int it = 0; it < nk; ++it) {
        const uint32_t stg_u = base + (uint32_t)(it % 3) * STG;

        if (it + 2 < nk) {
            issue((it + 2) << 5, base + (uint32_t)((it + 2) % 3) * STG);
            asm volatile("cp.async.wait_group 2;" ::: "memory");
        } else if (it + 1 < nk) {
            asm volatile("cp.async.wait_group 1;" ::: "memory");
        } else {
            asm volatile("cp.async.wait_group 0;" ::: "memory");
        }
        __syncthreads();

        if (wactive) {
            #pragma unroll
            for (int ks = 0; ks < 2; ++ks) {
                uint32_t aH[MTILES][4], aL[MTILES][4];
                {
                    const int arw = (lane & 15);
                    const int cA  = ks * 2 + (lane >> 4);
                    #pragma unroll
                    for (int mt = 0; mt < MTILES; ++mt) {
                        const int row = wm + mt * 16 + arw;
                        const uint32_t ad = stg_u + swz(row, cA);
                        ldm4(aH[mt][0], aH[mt][1], aH[mt][2], aH[mt][3], ad + 0);
                        ldm4(aL[mt][0], aL[mt][1], aL[mt][2], aL[mt][3], ad + OFF_A1_);
                    }
                }
                const int brw = (lane >> 4) * 8 + (lane & 7);
                const int cB  = ks * 2 + ((lane >> 3) & 1);
                #pragma unroll
                for (int p = 0; p < 4; ++p) {
                    uint32_t bH[4], bL[4];
                    const int row = wn + p * 16 + brw;
                    const uint32_t bd = stg_u + swz(row, cB);
                    ldm4(bH[0], bH[1], bH[2], bH[3], bd + OFF_B0_);
                    ldm4(bL[0], bL[1], bL[2], bL[3], bd + OFF_B1_);
                    #pragma unroll
                    for (int sub = 0; sub < 2; ++sub) {
                        const int nt = 2 * p + sub;
                        uint32_t b_h[2] = {bH[sub * 2], bH[sub * 2 + 1]};
                        uint32_t b_l[2] = {bL[sub * 2], bL[sub * 2 + 1]};
                        #pragma unroll
                        for (int mt = 0; mt < MTILES; ++mt) {
                            mma_f16(acc[mt][nt], aH[mt], b_h);
                            mma_f16(acc[mt][nt], aH[mt], b_l);
                            mma_f16(acc[mt][nt], aL[mt], b_h);
                        }
                    }
                }
            }
        }
        __syncthreads();
    }

    // ---- epilogue: stores ----
    const bool neven = ((N & 1) == 0);
    if (wactive) {
        #pragma unroll
        for (int mt = 0; mt < MTILES; ++mt) {
            #pragma unroll
            for (int half = 0; half < 2; ++half) {
                const int gm = m0 + wm + mt * 16 + g + half * 8;
                if (gm >= M) continue;
                const int orow = perm ? ((gm & 1023) * 30 + (gm >> 10)) : gm;
                #pragma unroll
                for (int nt = 0; nt < 8; ++nt) {
                    const int col = n0 + wn + nt * 8 + t * 2;
                    if (col >= N) continue;
                    float v0 = acc[mt][nt][half * 2 + 0];
                    float v1 = acc[mt][nt][half * 2 + 1];
                    if (bias) {
                        v0 += bias[col];
                        if (col + 1 < N) v1 += bias[col + 1];
                    }
                    if (Cf) {
                        if (neven && col + 1 < N) {
                            *(float2*)&Cf[(long)orow * N + col] = make_float2(v0, v1);
                        } else {
                            Cf[(long)orow * N + col] = v0;
                            if (col + 1 < N) Cf[(long)orow * N + col + 1] = v1;
                        }
                    }
                    if (C0 && neven && col + 1 < N) {
                        __half h0, l0, h1, l1;
                        f16split(v0, h0, l0);
                        f16split(v1, h1, l1);
                        *(__half2*)&C0[(long)orow * N + col] = __halves2half2(h0, h1);
                        *(__half2*)&C1[(long)orow * N + col] = __halves2half2(l0, l1);
                    }
                }
            }
        }
    }

    // ---- fused BN stats (raw accumulators; bias null for these layers) ----
    if (gsum) {
        float* ssum = (float*)smg;
        float* ssq2 = ssum + 128;
        if (tid < 256) ((float*)smg)[tid] = 0.0f;
        __syncthreads();
        if (wactive) {
            #pragma unroll
            for (int nt = 0; nt < 8; ++nt) {
                #pragma unroll
                for (int j = 0; j < 2; ++j) {
                    float s = 0.f, s2 = 0.f;
                    #pragma unroll
                    for (int mt = 0; mt < MTILES; ++mt) {
                        #pragma unroll
                        for (int half = 0; half < 2; ++half) {
                            const float v = acc[mt][nt][half * 2 + j];
                            s += v; s2 += v * v;
                        }
                    }
                    #pragma unroll
                    for (int o = 16; o >= 4; o >>= 1) {
                        s  += __shfl_down_sync(0xffffffffu, s,  o);
                        s2 += __shfl_down_sync(0xffffffffu, s2, o);
                    }
                    if (g == 0) {
                        const int cl = wn + nt * 8 + t * 2 + j;
                        atomicAdd(&ssum[cl], s);
                        atomicAdd(&ssq2[cl], s2);
                    }
                }
            }
        }
        __syncthreads();
        if (tid < 128 && n0 + tid < N) {
            atomicAdd(&gsum[(n0 + tid) & 511], ssum[tid]);
            atomicAdd(&gssq[(n0 + tid) & 511], ssq2[tid]);
        }
    }
}

constexpr int DS2 = 3 * (2 * 128 * 64 + 2 * 128 * 64) + 1024;   // 99328
constexpr int DS1 = 3 * (2 * 64 * 64 + 2 * 128 * 64) + 1024;    // 74752

// ======================= single prep kernel ================================
__global__ void prep_all(const float* __restrict__ w_e1, const float* __restrict__ w_e2,
                         const float* __restrict__ w_e3, const float* __restrict__ w_d1,
                         const float* __restrict__ w_d2, const float* __restrict__ w_d3,
                         const float* __restrict__ W_in, const float* __restrict__ W_q,
                         const float* __restrict__ W_out, const float* __restrict__ cb,
                         const float* __restrict__ input,
                         __half* hb, float* cn, float* stats, float* loss, int* cnt)
{
    const int  job = blockIdx.y;
    const long tid0 = (long)blockIdx.x * blockDim.x + threadIdx.x;
    const long strd = (long)gridDim.x * blockDim.x;

    auto enc = [&](const float* w, __half* h0, __half* h1, int Kk, int Kp) {
        const int I = 512, Ke = I * Kk;
        const long n = 512L * Kp;
        for (long j = tid0; j < n; j += strd) {
            const int o  = (int)(j / Kp);
            const int kk = (int)(j % Kp);
            float x = 0.f;
            if (kk < Ke) x = w[(long)o * Ke + (long)(kk % I) * Kk + (kk / I)];
            __half h, l; f16split(x, h, l);
            h0[j] = h; h1[j] = l;
        }
    };
    auto dec = [&](const float* w, __half* h0, __half* h1, int Kk) {
        const int I = 512, O = 512;
        const long n = (long)Kk * O * I;
        for (long j = tid0; j < n; j += strd) {
            const int i  = (int)(j % I);
            const int nn = (int)(j / I);
            const int o  = nn % O;
            const int k  = nn / O;
            const float x = w[(long)i * O * Kk + (long)o * Kk + k];
            __half h, l; f16split(x, h, l);
            h0[j] = h; h1[j] = l;
        }
    };
    auto tr = [&](const float* in, __half* h0, __half* h1, int R, int C, int Kp) {
        const long n = (long)C * Kp;
        for (long j = tid0; j < n; j += strd) {
            const int c = (int)(j / Kp);
            const int r = (int)(j % Kp);
            const float x = (r < R) ? in[(long)r * C + c] : 0.f;
            __half h, l; f16split(x, h, l);
            h0[j] = h; h1[j] = l;
        }
    };

    switch (job) {
    case 0: enc(w_e1, hb + H_WE1, hb + H_WE1 + 512L * 2560, 5, 2560); break;
    case 1: enc(w_e2, hb + H_WE2, hb + H_WE2 + 512L * 1536, 3, 1536); break;
    case 2: enc(w_e3, hb + H_WE3, hb + H_WE3 + 512L * 1024, 2, 1024); break;
    case 3: dec(w_d1, hb + H_WD1, hb + H_WD1 + 1024L * 512, 2); break;
    case 4: dec(w_d2, hb + H_WD2, hb + H_WD2 + 1536L * 512, 3); break;
    case 5: dec(w_d3, hb + H_WD3, hb + H_WD3 + 2560L * 512, 5); break;
    case 6: tr(W_in,  hb + H_WIT, hb + H_WIT + 512L * 160, 135, 512, 160); break;
    case 7: tr(W_q,   hb + H_WQT, hb + H_WQT + 512L * 512, 512, 512, 512); break;
    case 8: tr(W_out, hb + H_WOT, hb + H_WOT + 135L * 512, 512, 135, 512); break;
    case 9: {
        __half* h0 = hb + H_CB; __half* h1 = h0 + 512L * 512;
        for (long j = tid0; j < 512L * 512; j += strd) {
            __half h, l; f16split(cb[j], h, l);
            h0[j] = h; h1[j] = l;
        }
        break;
    }
    case 10: {
        __half* h0 = hb + H_XIN; __half* h1 = h0 + 30720L * 160;
        const long n = 30720L * 160;
        for (long j = tid0; j < n; j += strd) {
            const long r = j / 160;
            const int  c = (int)(j % 160);
            const float x = (c < 135) ? input[r * 135 + c] : 0.f;
            __half h, l; f16split(x, h, l);
            h0[j] = h; h1[j] = l;
        }
        break;
    }
    case 11: {
        for (long j = tid0; j < 6L * 2 * 512; j += strd) stats[j] = 0.0f;
        for (long j = tid0; j < 512; j += strd) cnt[j] = 0;
        if (tid0 == 0) loss[0] = 0.0f;
        for (long k = tid0; k < 512; k += strd) {
            float s = 0.f;
            for (int d = 0; d < 512; ++d) {
                const float v = cb[k * 512 + d];
                s += v * v;
            }
            cn[k] = s;
        }
        break;
    }
    }
}

// ======================= BN normalize (+ReLU), 4-wide, smem LUT =============
__global__ void bn_norm2(const float* __restrict__ X,
                         const float* __restrict__ gamma, const float* __restrict__ beta,
                         const float* __restrict__ gsum, const float* __restrict__ gssq,
                         int M, __half* __restrict__ h0, __half* __restrict__ h1)
{
    __shared__ float s_scale[512], s_shift[512];
    const float invM = 1.0f / (float)M;
    for (int c = threadIdx.x; c < 512; c += blockDim.x) {
        const float mn = gsum[c] * invM;
        const float vr = gssq[c] * invM - mn * mn;
        const float sc = rsqrtf(vr + EPSV) * gamma[c];
        s_scale[c] = sc;
        s_shift[c] = beta[c] - mn * sc;
    }
    __syncthreads();

    const int total4 = (M * 512) >> 2;
    for (int i4 = blockIdx.x * blockDim.x + threadIdx.x; i4 < total4;
         i4 += gridDim.x * blockDim.x) {
        const long i = (long)i4 << 2;
        const int c0 = (int)(i & 511);
        const float4 x = *(const float4*)&X[i];
        const float v[4] = {x.x, x.y, x.z, x.w};
        __half hh[4], ll[4];
        #pragma unroll
        for (int j = 0; j < 4; ++j) {
            float y = fmaf(v[j], s_scale[c0 + j], s_shift[c0 + j]);
            y = y > 0.0f ? y : 0.0f;
            f16split(y, hh[j], ll[j]);
        }
        *(__half2*)&h0[i]     = __halves2half2(hh[0], hh[1]);
        *(__half2*)&h0[i + 2] = __halves2half2(hh[2], hh[3]);
        *(__half2*)&h1[i]     = __halves2half2(ll[0], ll[1]);
        *(__half2*)&h1[i + 2] = __halves2half2(ll[2], ll[3]);
    }
}

// ======================= vector quantization ================================
// argmin + split-f16 q copy + counts + loss; z-norm recomputed inline.
__global__ void vq_argmin(const float* __restrict__ scores, const float* __restrict__ cnorm,
                          const float* __restrict__ cb,
                          const __half* __restrict__ cb0, const __half* __restrict__ cb1,
                          const float* __restrict__ zr,
                          const float* __restrict__ zsum, const float* __restrict__ zssq,
                          const float* __restrict__ zg, const float* __restrict__ zb,
                          __half* __restrict__ qh, __half* __restrict__ ql,
                          int* __restrict__ counts, float* __restrict__ loss)
{
    const int n = blockIdx.x;
    const int k = threadIdx.x;
    const float d = cnorm[k] - 2.0f * scores[(long)n * 512 + k];
    __shared__ float sv[512];
    __shared__ int   si[512];
    sv[k] = d; si[k] = k;
    __syncthreads();
    for (int st = 256; st > 0; st >>= 1) {
        if (k < st) {
            const float ov = sv[k + st];
            const int   oi = si[k + st];
            if (ov < sv[k] || (ov == sv[k] && oi < si[k])) { sv[k] = ov; si[k] = oi; }
        }
        __syncthreads();
    }
    const int best = si[0];
    __syncthreads();

    qh[(long)n * 512 + k] = cb0[(long)best * 512 + k];
    ql[(long)n * 512 + k] = cb1[(long)best * 512 + k];

    const float invM = 1.0f / 1024.0f;
    const float mn = zsum[k] * invM;
    const float vr = zssq[k] * invM - mn * mn;
    const float sc = rsqrtf(vr + EPSV) * zg[k];
    float zn = fmaf(zr[(long)n * 512 + k], sc, zb[k] - mn * sc);
    zn = zn > 0.f ? zn : 0.f;

    const float diff = cb[(long)best * 512 + k] - zn;
    sv[k] = diff * diff;
    __syncthreads();
    for (int st = 256; st > 0; st >>= 1) {
        if (k < st) sv[k] += sv[k + st];
        __syncthreads();
    }
    if (k == 0) {
        atomicAdd(&counts[best], 1);
        atomicAdd(loss, sv[0]);
    }
}

__global__ void finalize_k(const int* __restrict__ counts, const float* __restrict__ loss,
                           float* __restrict__ out, long outsize)
{
    const int k = threadIdx.x;
    const float p = (float)counts[k] * (1.0f / 1024.0f);
    __shared__ float sh[512];
    sh[k] = p * logf(p + 1e-10f);
    __syncthreads();
    for (int st = 256; st > 0; st >>= 1) {
        if (k < st) sh[k] += sh[k + st];
        __syncthreads();
    }
    if (k == 0) {
        const long R = 1024L * 30 * 135;
        if (outsize >= R + 2) {
            out[R]     = loss[0] * 1.25f / (1024.0f * 512.0f);
            out[R + 1] = expf(-sh[0]);
        }
    }
}

// ======================= host launch ========================================
static inline dim3 grid128(int M, int N) { return dim3((N + 127) / 128, (M + 127) / 128); }
static inline dim3 grid64(int M, int N)  { return dim3((N + 127) / 128, (M + 63) / 64); }

extern "C" void kernel_launch(void* const* d_in, const int* in_sizes, int n_in,
                              void* d_out, int out_size)
{
    (void)in_sizes; (void)n_in;
    float* buf = nullptr;
    __half* hb = nullptr;
    cudaGetSymbolAddress((void**)&buf, g_buf);
    cudaGetSymbolAddress((void**)&hb, g_hbuf);
    cudaFuncSetAttribute(gemm_hh<2>, cudaFuncAttributeMaxDynamicSharedMemorySize, DS2);
    cudaFuncSetAttribute(gemm_hh<1>, cudaFuncAttributeMaxDynamicSharedMemorySize, DS1);

    const float* input = (const float*)d_in[0];
    const float* W_in  = (const float*)d_in[1];
    const float* b_in  = (const float*)d_in[2];
    const float* w_e1  = (const float*)d_in[3];
    const float* g_e1  = (const float*)d_in[4];
    const float* b_e1  = (const float*)d_in[5];
    const float* w_e2  = (const float*)d_in[6];
    const float* g_e2  = (const float*)d_in[7];
    const float* b_e2  = (const float*)d_in[8];
    const float* w_e3  = (const float*)d_in[9];
    const float* g_e3  = (const float*)d_in[10];
    const float* b_e3  = (const float*)d_in[11];
    const float* cb    = (const float*)d_in[12];
    const float* W_q   = (const float*)d_in[13];
    const float* b_q   = (const float*)d_in[14];
    const float* w_d1  = (const float*)d_in[15];
    const float* g_d1  = (const float*)d_in[16];
    const float* b_d1  = (const float*)d_in[17];
    const float* w_d2  = (const float*)d_in[18];
    const float* g_d2  = (const float*)d_in[19];
    const float* b_d2  = (const float*)d_in[20];
    const float* w_d3  = (const float*)d_in[21];
    const float* g_d3  = (const float*)d_in[22];
    const float* b_d3  = (const float*)d_in[23];
    const float* W_out = (const float*)d_in[24];
    const float* b_out = (const float*)d_in[25];

    float* e1r  = buf + O_E1R;
    float* e2r  = buf + O_E2R;
    float* zr   = buf + O_ZR;
    float* d1r  = buf + O_D1R;
    float* d2r  = buf + O_D2R;
    float* d3r  = buf + O_D3R;
    float* sc   = buf + O_SC;
    float* cn   = buf + O_CN;
    float* stats= buf + O_STAT;
    float* loss = buf + O_LOSS;
    int*   cnt  = (int*)(buf + O_CNT);

    __half* we1_0 = hb + H_WE1; __half* we1_1 = we1_0 + 512L * 2560;
    __half* we2_0 = hb + H_WE2; __half* we2_1 = we2_0 + 512L * 1536;
    __half* we3_0 = hb + H_WE3; __half* we3_1 = we3_0 + 512L * 1024;
    __half* wd1_0 = hb + H_WD1; __half* wd1_1 = wd1_0 + 1024L * 512;
    __half* wd2_0 = hb + H_WD2; __half* wd2_1 = wd2_0 + 1536L * 512;
    __half* wd3_0 = hb + H_WD3; __half* wd3_1 = wd3_0 + 2560L * 512;
    __half* wit_0 = hb + H_WIT; __half* wit_1 = wit_0 + 512L * 160;
    __half* wqt_0 = hb + H_WQT; __half* wqt_1 = wqt_0 + 512L * 512;
    __half* wot_0 = hb + H_WOT; __half* wot_1 = wot_0 + 135L * 512;
    __half* cb_0  = hb + H_CB;  __half* cb_1  = cb_0  + 512L * 512;
    __half* xin_0 = hb + H_XIN; __half* xin_1 = xin_0 + 30720L * 160;
    __half* x0_0  = hb + H_X0;  __half* x0_1  = x0_0  + 30720L * 512;
    __half* e1_0  = hb + H_E1;  __half* e1_1  = e1_0  + 6144L * 512;
    __half* e2_0  = hb + H_E2;  __half* e2_1  = e2_0  + 2048L * 512;
    __half* z_0   = hb + H_Z;   __half* z_1   = z_0   + 1024L * 512;
    __half* q_0   = hb + H_Q;   __half* q_1   = q_0   + 1024L * 512;
    __half* d0_0  = hb + H_D0;  __half* d0_1  = d0_0  + 1024L * 512;
    __half* d1_0  = hb + H_D1;  __half* d1_1  = d1_0  + 1024L * 1024;
    __half* d2_0  = hb + H_D2;  __half* d2_1  = d2_0  + 2048L * 1536;
    __half* d3_0  = hb + H_D3;  __half* d3_1  = d3_0  + 30720L * 512;

    float* out = (float*)d_out;

    // ---- prep: everything in ONE launch ----
    prep_all<<<dim3(160, 12), 256>>>(w_e1, w_e2, w_e3, w_d1, w_d2, w_d3,
                                     W_in, W_q, W_out, cb, input,
                                     hb, cn, stats, loss, cnt);

    float* st0 = stats;
    float* st1 = stats + 1024;
    float* st2 = stats + 2048;
    float* st3 = stats + 3072;
    float* st4 = stats + 4096;
    float* st5 = stats + 5120;

    // ---- input GEMM: K=135(pad160) -> 512, split-only out, perm ----
    gemm_hh<2><<<grid128(30720, 512), 256, DS2>>>(
        xin_0, xin_1, wit_0, wit_1, b_in, nullptr, x0_0, x0_1,
        nullptr, nullptr, 30720, 512, 160, 1);

    // ---- encoder (stats fused into GEMM epilogues) ----
    gemm_hh<2><<<grid128(6144, 512), 256, DS2>>>(
        x0_0, x0_1, we1_0, we1_1, nullptr, e1r, nullptr, nullptr,
        st0, st0 + 512, 6144, 512, 2560, 0);
    bn_norm2<<<2048, 256>>>(e1r, g_e1, b_e1, st0, st0 + 512, 6144, e1_0, e1_1);

    gemm_hh<1><<<grid64(2048, 512), 256, DS1>>>(
        e1_0, e1_1, we2_0, we2_1, nullptr, e2r, nullptr, nullptr,
        st1, st1 + 512, 2048, 512, 1536, 0);
    bn_norm2<<<1024, 256>>>(e2r, g_e2, b_e2, st1, st1 + 512, 2048, e2_0, e2_1);

    gemm_hh<1><<<grid64(1024, 512), 256, DS1>>>(
        e2_0, e2_1, we3_0, we3_1, nullptr, zr, nullptr, nullptr,
        st2, st2 + 512, 1024, 512, 1024, 0);
    bn_norm2<<<512, 256>>>(zr, g_e3, b_e3, st2, st2 + 512, 1024, z_0, z_1);

    // ---- vector quantization ----
    gemm_hh<1><<<grid64(1024, 512), 256, DS1>>>(
        z_0, z_1, cb_0, cb_1, nullptr, sc, nullptr, nullptr,
        nullptr, nullptr, 1024, 512, 512, 0);
    vq_argmin<<<1024, 512>>>(sc, cn, cb, cb_0, cb_1,
                             zr, st2, st2 + 512, g_e3, b_e3,
                             q_0, q_1, cnt, loss);

    // ---- decoder ----
    gemm_hh<1><<<grid64(1024, 512), 256, DS1>>>(
        q_0, q_1, wqt_0, wqt_1, b_q, nullptr, d0_0, d0_1,
        nullptr, nullptr, 1024, 512, 512, 0);

    gemm_hh<1><<<grid64(1024, 1024), 256, DS1>>>(
        d0_0, d0_1, wd1_0, wd1_1, nullptr, d1r, nullptr, nullptr,
        st3, st3 + 512, 1024, 1024, 512, 0);
    bn_norm2<<<1024, 256>>>(d1r, g_d1, b_d1, st3, st3 + 512, 2048, d1_0, d1_1);

    gemm_hh<2><<<grid128(2048, 1536), 256, DS2>>>(
        d1_0, d1_1, wd2_0, wd2_1, nullptr, d2r, nullptr, nullptr,
        st4, st4 + 512, 2048, 1536, 512, 0);
    bn_norm2<<<2048, 256>>>(d2r, g_d2, b_d2, st4, st4 + 512, 6144, d2_0, d2_1);

    gemm_hh<2><<<grid128(6144, 2560), 256, DS2>>>(
        d2_0, d2_1, wd3_0, wd3_1, nullptr, d3r, nullptr, nullptr,
        st5, st5 + 512, 6144, 2560, 512, 0);
    bn_norm2<<<2048, 256>>>(d3r, g_d3, b_d3, st5, st5 + 512, 30720, d3_0, d3_1);

    // ---- output GEMM -> recon ----
    gemm_hh<2><<<grid128(30720, 135), 256, DS2>>>(
        d3_0, d3_1, wot_0, wot_1, b_out, out, nullptr, nullptr,
        nullptr, nullptr, 30720, 135, 512, 0);

    // ---- scalars ----
    finalize_k<<<1, 512>>>(cnt, loss, out, (long)out_size);
}

// round 15
// speedup vs baseline: 1.0520x; 1.0196x over previous
#include <cuda_runtime.h>
#include <cuda_fp16.h>
#include <math.h>
#include <stdint.h>

// ---------------------------------------------------------------------------
// VQ-VAE forward. T=30, B=1024, D_POSE=135, H=512, K_CODES=512.
// Row-major GEMMs C[M,N] = A[M,K] * B'[N,K]^T, mma.sync.m16n8k16 f16,
// 3xFP16 hi/lo split (err ~2^-24). All operands pre-split f16 in gmem;
// mainloop pure cp.async + ldmatrix + mma. 3-stage pipeline, 64B swizzled
// rows, 2 CTAs/SM. BN stats fused into producer epilogues; normalize is a
// separate vectorized pass (A-load fusion measured slower twice, R12/R13).
// R15: 64x64 tile instance for small GEMMs (fills the chip), finalize
// folded into vq_argmin via last-block ticket.
// ---------------------------------------------------------------------------

#define EPSV 1e-5f

// ======================= fp32 scratch ======================================
constexpr long O_E1R = 0;                        // 6144 x 512 (raw, pre-BN)
constexpr long O_E2R = O_E1R + 6144L * 512;      // 2048 x 512
constexpr long O_ZR  = O_E2R + 2048L * 512;      // 1024 x 512
constexpr long O_D1R = O_ZR  + 1024L * 512;      // 1024 x 1024
constexpr long O_D2R = O_D1R + 1024L * 1024;     // 2048 x 1536
constexpr long O_D3R = O_D2R + 2048L * 1536;     // 6144 x 2560
constexpr long O_SC  = O_D3R + 6144L * 2560;     // 1024 x 512
constexpr long O_CN  = O_SC  + 1024L * 512;      // 512
constexpr long O_STAT= O_CN  + 512;              // 6 x 2 x 512
constexpr long O_LOSS= O_STAT+ 6L * 2 * 512;     // [0]=loss, [1]=ticket(int)
constexpr long O_CNT = O_LOSS+ 512;
constexpr long TOTALF= O_CNT + 512;

__device__ float g_buf[TOTALF];

// ======================= f16 split scratch (hi then lo per buffer) =========
constexpr long H_WE1 = 0;                          // [512,2560]
constexpr long H_WE2 = H_WE1 + 2L * 512 * 2560;    // [512,1536]
constexpr long H_WE3 = H_WE2 + 2L * 512 * 1536;    // [512,1024]
constexpr long H_WD1 = H_WE3 + 2L * 512 * 1024;    // [1024,512]
constexpr long H_WD2 = H_WD1 + 2L * 1024 * 512;    // [1536,512]
constexpr long H_WD3 = H_WD2 + 2L * 1536 * 512;    // [2560,512]
constexpr long H_WIT = H_WD3 + 2L * 2560 * 512;    // [512,160]
constexpr long H_WQT = H_WIT + 2L * 512 * 160;     // [512,512]
constexpr long H_WOT = H_WQT + 2L * 512 * 512;     // [135,512]
constexpr long H_CB  = H_WOT + 2L * 135 * 512;     // [512,512]
constexpr long H_XIN = H_CB  + 2L * 512 * 512;     // [30720,160]
constexpr long H_X0  = H_XIN + 2L * 30720 * 160;   // [30720,512]
constexpr long H_E1  = H_X0  + 2L * 30720 * 512;   // [6144,512]
constexpr long H_E2  = H_E1  + 2L * 6144 * 512;    // [2048,512]
constexpr long H_Z   = H_E2  + 2L * 2048 * 512;    // [1024,512]
constexpr long H_Q   = H_Z   + 2L * 1024 * 512;    // [1024,512]
constexpr long H_D0  = H_Q   + 2L * 1024 * 512;    // [1024,512]
constexpr long H_D1  = H_D0  + 2L * 1024 * 512;    // [1024,1024]
constexpr long H_D2  = H_D1  + 2L * 1024 * 1024;   // [2048,1536]
constexpr long H_D3  = H_D2  + 2L * 2048 * 1536;   // [30720,512]
constexpr long TOTALH= H_D3  + 2L * 30720 * 512;

__device__ __half g_hbuf[TOTALH];

// ======================= helpers ===========================================
__device__ __forceinline__ uint32_t smem_u32(const void* p)
{
    return (uint32_t)__cvta_generic_to_shared(p);
}

__device__ __forceinline__ void f16split(float x, __half& h, __half& l)
{
    h = __float2half_rn(x);
    l = __float2half_rn(x - __half2float(h));
}

__device__ __forceinline__ void mma_f16(float* c, const uint32_t* a, const uint32_t* b)
{
    asm volatile(
        "mma.sync.aligned.m16n8k16.row.col.f32.f16.f16.f32 "
        "{%0,%1,%2,%3}, {%4,%5,%6,%7}, {%8,%9}, {%0,%1,%2,%3};"
        : "+f"(c[0]), "+f"(c[1]), "+f"(c[2]), "+f"(c[3])
        : "r"(a[0]), "r"(a[1]), "r"(a[2]), "r"(a[3]), "r"(b[0]), "r"(b[1]));
}

__device__ __forceinline__ void ldm4(uint32_t& r0, uint32_t& r1, uint32_t& r2,
                                     uint32_t& r3, uint32_t addr)
{
    asm volatile("ldmatrix.sync.aligned.m8n8.x4.shared.b16 {%0,%1,%2,%3}, [%4];"
                 : "=r"(r0), "=r"(r1), "=r"(r2), "=r"(r3) : "r"(addr));
}

__device__ __forceinline__ void cp16(uint32_t dst, const void* src, int pred)
{
    asm volatile("cp.async.cg.shared.global [%0], [%1], 16, %2;"
                 :: "r"(dst), "l"(src), "r"(pred ? 16 : 0) : "memory");
}
__device__ __forceinline__ void cp_commit()
{
    asm volatile("cp.async.commit_group;" ::: "memory");
}

// 64B rows, chunk swizzle: byte = row*64 + ((ch ^ ((row>>1)&3)) * 16)
__device__ __forceinline__ uint32_t swz(int row, int ch)
{
    return (uint32_t)(row * 64 + ((ch ^ ((row >> 1) & 3)) << 4));
}

// ======================= GEMM ==============================================
// CTA tile (64*MTILES) x (64*NTILES), BK=32 halves, 256 threads, 8 warps
// (4M x 2N), warp tile (16*MTILES) x (32*NTILES). 3-stage cp.async pipeline,
// swizzled 64B rows, 2 CTAs/SM. Inactive N-edge warps skip MMA work.

template<int MTILES, int NTILES>
__global__ __launch_bounds__(256, 2)
void gemm_hh(const __half* __restrict__ A0, const __half* __restrict__ A1,
             const __half* __restrict__ B0, const __half* __restrict__ B1,
             const float* __restrict__ bias, float* __restrict__ Cf,
             __half* __restrict__ C0, __half* __restrict__ C1,
             float* __restrict__ gsum, float* __restrict__ gssq,
             int M, int N, int Kp, int perm)
{
    constexpr int AROWS   = 64 * MTILES;
    constexpr int BROWS   = 64 * NTILES;
    constexpr int NT      = 4 * NTILES;          // n-subtiles per warp
    constexpr int OFF_A1_ = AROWS * 64;
    constexpr int OFF_B0_ = 2 * AROWS * 64;
    constexpr int OFF_B1_ = OFF_B0_ + BROWS * 64;
    constexpr int STG     = OFF_B0_ + 2 * BROWS * 64;

    extern __shared__ char dsm[];
    const uint32_t dynb = smem_u32(dsm);
    const uint32_t base = (dynb + 1023u) & ~1023u;
    char* smg = dsm + (base - dynb);

    const int tid  = threadIdx.x;
    const int wid  = tid >> 5;
    const int lane = tid & 31;
    const int wm   = (wid & 3) * (16 * MTILES);
    const int wn   = (wid >> 2) * (32 * NTILES);
    const int g    = lane >> 2;
    const int t    = lane & 3;
    const int m0   = blockIdx.y * AROWS;
    const int n0   = blockIdx.x * BROWS;
    const bool wactive = (n0 + wn) < N;

    const int nk = Kp >> 5;

    auto issue = [&](int k0, uint32_t stg) {
        #pragma unroll
        for (int i = 0; i < MTILES; ++i) {
            const int slot = tid + i * 256;
            const int row = slot >> 2, ch = slot & 3;
            const int gm = m0 + row;
            const int ok = gm < M;
            const long off = (long)(ok ? gm : 0) * Kp + ch * 8 + k0;
            const uint32_t d = swz(row, ch);
            cp16(stg + 0       + d, A0 + off, ok);
            cp16(stg + OFF_A1_ + d, A1 + off, ok);
        }
        #pragma unroll
        for (int i = 0; i < NTILES; ++i) {
            const int slot = tid + i * 256;
            const int row = slot >> 2, ch = slot & 3;
            const int gn = n0 + row;
            const int ok = gn < N;
            const long off = (long)(ok ? gn : 0) * Kp + ch * 8 + k0;
            const uint32_t d = swz(row, ch);
            cp16(stg + OFF_B0_ + d, B0 + off, ok);
            cp16(stg + OFF_B1_ + d, B1 + off, ok);
        }
        cp_commit();
    };

    float acc[MTILES][NT][4];
    #pragma unroll
    for (int a = 0; a < MTILES; a++)
        #pragma unroll
        for (int b = 0; b < NT; b++)
            #pragma unroll
            for (int c = 0; c < 4; c++) acc[a][b][c] = 0.f;

    issue(0, base);
    if (nk > 1) issue(32, base + STG);

    for (int it = 0; it < nk; ++it) {
        const uint32_t stg_u = base + (uint32_t)(it % 3) * STG;

        if (it + 2 < nk) {
            issue((it + 2) << 5, base + (uint32_t)((it + 2) % 3) * STG);
            asm volatile("cp.async.wait_group 2;" ::: "memory");
        } else if (it + 1 < nk) {
            asm volatile("cp.async.wait_group 1;" ::: "memory");
        } else {
            asm volatile("cp.async.wait_group 0;" ::: "memory");
        }
        __syncthreads();

        if (wactive) {
            #pragma unroll
            for (int ks = 0; ks < 2; ++ks) {
                uint32_t aH[MTILES][4], aL[MTILES][4];
                {
                    const int arw = (lane & 15);
                    const int cA  = ks * 2 + (lane >> 4);
                    #pragma unroll
                    for (int mt = 0; mt < MTILES; ++mt) {
                        const int row = wm + mt * 16 + arw;
                        const uint32_t ad = stg_u + swz(row, cA);
                        ldm4(aH[mt][0], aH[mt][1], aH[mt][2], aH[mt][3], ad + 0);
                        ldm4(aL[mt][0], aL[mt][1], aL[mt][2], aL[mt][3], ad + OFF_A1_);
                    }
                }
                const int brw = (lane >> 4) * 8 + (lane & 7);
                const int cB  = ks * 2 + ((lane >> 3) & 1);
                #pragma unroll
                for (int p = 0; p < 2 * NTILES; ++p) {
                    uint32_t bH[4], bL[4];
                    const int row = wn + p * 16 + brw;
                    const uint32_t bd = stg_u + swz(row, cB);
                    ldm4(bH[0], bH[1], bH[2], bH[3], bd + OFF_B0_);
                    ldm4(bL[0], bL[1], bL[2], bL[3], bd + OFF_B1_);
                    #pragma unroll
                    for (int sub = 0; sub < 2; ++sub) {
                        const int nt = 2 * p + sub;
                        uint32_t b_h[2] = {bH[sub * 2], bH[sub * 2 + 1]};
                        uint32_t b_l[2] = {bL[sub * 2], bL[sub * 2 + 1]};
                        #pragma unroll
                        for (int mt = 0; mt < MTILES; ++mt) {
                            mma_f16(acc[mt][nt], aH[mt], b_h);
                            mma_f16(acc[mt][nt], aH[mt], b_l);
                            mma_f16(acc[mt][nt], aL[mt], b_h);
                        }
                    }
                }
            }
        }
        __syncthreads();
    }

    // ---- epilogue: stores ----
    const bool neven = ((N & 1) == 0);
    if (wactive) {
        #pragma unroll
        for (int mt = 0; mt < MTILES; ++mt) {
            #pragma unroll
            for (int half = 0; half < 2; ++half) {
                const int gm = m0 + wm + mt * 16 + g + half * 8;
                if (gm >= M) continue;
                const int orow = perm ? ((gm & 1023) * 30 + (gm >> 10)) : gm;
                #pragma unroll
                for (int nt = 0; nt < NT; ++nt) {
                    const int col = n0 + wn + nt * 8 + t * 2;
                    if (col >= N) continue;
                    float v0 = acc[mt][nt][half * 2 + 0];
                    float v1 = acc[mt][nt][half * 2 + 1];
                    if (bias) {
                        v0 += bias[col];
                        if (col + 1 < N) v1 += bias[col + 1];
                    }
                    if (Cf) {
                        if (neven && col + 1 < N) {
                            *(float2*)&Cf[(long)orow * N + col] = make_float2(v0, v1);
                        } else {
                            Cf[(long)orow * N + col] = v0;
                            if (col + 1 < N) Cf[(long)orow * N + col + 1] = v1;
                        }
                    }
                    if (C0 && neven && col + 1 < N) {
                        __half h0, l0, h1, l1;
                        f16split(v0, h0, l0);
                        f16split(v1, h1, l1);
                        *(__half2*)&C0[(long)orow * N + col] = __halves2half2(h0, h1);
                        *(__half2*)&C1[(long)orow * N + col] = __halves2half2(l0, l1);
                    }
                }
            }
        }
    }

    // ---- fused BN stats (raw accumulators; bias null for these layers) ----
    if (gsum) {
        float* ssum = (float*)smg;          // [BROWS]
        float* ssq2 = ssum + BROWS;         // [BROWS]
        if (tid < 2 * BROWS) ((float*)smg)[tid] = 0.0f;
        __syncthreads();
        if (wactive) {
            #pragma unroll
            for (int nt = 0; nt < NT; ++nt) {
                #pragma unroll
                for (int j = 0; j < 2; ++j) {
                    float s = 0.f, s2 = 0.f;
                    #pragma unroll
                    for (int mt = 0; mt < MTILES; ++mt) {
                        #pragma unroll
                        for (int half = 0; half < 2; ++half) {
                            const float v = acc[mt][nt][half * 2 + j];
                            s += v; s2 += v * v;
                        }
                    }
                    #pragma unroll
                    for (int o = 16; o >= 4; o >>= 1) {
                        s  += __shfl_down_sync(0xffffffffu, s,  o);
                        s2 += __shfl_down_sync(0xffffffffu, s2, o);
                    }
                    if (g == 0) {
                        const int cl = wn + nt * 8 + t * 2 + j;
                        atomicAdd(&ssum[cl], s);
                        atomicAdd(&ssq2[cl], s2);
                    }
                }
            }
        }
        __syncthreads();
        if (tid < BROWS && n0 + tid < N) {
            atomicAdd(&gsum[(n0 + tid) & 511], ssum[tid]);
            atomicAdd(&gssq[(n0 + tid) & 511], ssq2[tid]);
        }
    }
}

constexpr int DS22 = 3 * (2 * 128 * 64 + 2 * 128 * 64) + 1024;   // 99328
constexpr int DS11 = 3 * (2 * 64 * 64 + 2 * 64 * 64) + 1024;     // 50176

// ======================= single prep kernel ================================
__global__ void prep_all(const float* __restrict__ w_e1, const float* __restrict__ w_e2,
                         const float* __restrict__ w_e3, const float* __restrict__ w_d1,
                         const float* __restrict__ w_d2, const float* __restrict__ w_d3,
                         const float* __restrict__ W_in, const float* __restrict__ W_q,
                         const float* __restrict__ W_out, const float* __restrict__ cb,
                         const float* __restrict__ input,
                         __half* hb, float* cn, float* stats, float* loss, int* cnt)
{
    const int  job = blockIdx.y;
    const long tid0 = (long)blockIdx.x * blockDim.x + threadIdx.x;
    const long strd = (long)gridDim.x * blockDim.x;

    auto enc = [&](const float* w, __half* h0, __half* h1, int Kk, int Kp) {
        const int I = 512, Ke = I * Kk;
        const long n = 512L * Kp;
        for (long j = tid0; j < n; j += strd) {
            const int o  = (int)(j / Kp);
            const int kk = (int)(j % Kp);
            float x = 0.f;
            if (kk < Ke) x = w[(long)o * Ke + (long)(kk % I) * Kk + (kk / I)];
            __half h, l; f16split(x, h, l);
            h0[j] = h; h1[j] = l;
        }
    };
    auto dec = [&](const float* w, __half* h0, __half* h1, int Kk) {
        const int I = 512, O = 512;
        const long n = (long)Kk * O * I;
        for (long j = tid0; j < n; j += strd) {
            const int i  = (int)(j % I);
            const int nn = (int)(j / I);
            const int o  = nn % O;
            const int k  = nn / O;
            const float x = w[(long)i * O * Kk + (long)o * Kk + k];
            __half h, l; f16split(x, h, l);
            h0[j] = h; h1[j] = l;
        }
    };
    auto tr = [&](const float* in, __half* h0, __half* h1, int R, int C, int Kp) {
        const long n = (long)C * Kp;
        for (long j = tid0; j < n; j += strd) {
            const int c = (int)(j / Kp);
            const int r = (int)(j % Kp);
            const float x = (r < R) ? in[(long)r * C + c] : 0.f;
            __half h, l; f16split(x, h, l);
            h0[j] = h; h1[j] = l;
        }
    };

    switch (job) {
    case 0: enc(w_e1, hb + H_WE1, hb + H_WE1 + 512L * 2560, 5, 2560); break;
    case 1: enc(w_e2, hb + H_WE2, hb + H_WE2 + 512L * 1536, 3, 1536); break;
    case 2: enc(w_e3, hb + H_WE3, hb + H_WE3 + 512L * 1024, 2, 1024); break;
    case 3: dec(w_d1, hb + H_WD1, hb + H_WD1 + 1024L * 512, 2); break;
    case 4: dec(w_d2, hb + H_WD2, hb + H_WD2 + 1536L * 512, 3); break;
    case 5: dec(w_d3, hb + H_WD3, hb + H_WD3 + 2560L * 512, 5); break;
    case 6: tr(W_in,  hb + H_WIT, hb + H_WIT + 512L * 160, 135, 512, 160); break;
    case 7: tr(W_q,   hb + H_WQT, hb + H_WQT + 512L * 512, 512, 512, 512); break;
    case 8: tr(W_out, hb + H_WOT, hb + H_WOT + 135L * 512, 512, 135, 512); break;
    case 9: {
        __half* h0 = hb + H_CB; __half* h1 = h0 + 512L * 512;
        for (long j = tid0; j < 512L * 512; j += strd) {
            __half h, l; f16split(cb[j], h, l);
            h0[j] = h; h1[j] = l;
        }
        break;
    }
    case 10: {
        __half* h0 = hb + H_XIN; __half* h1 = h0 + 30720L * 160;
        const long n = 30720L * 160;
        for (long j = tid0; j < n; j += strd) {
            const long r = j / 160;
            const int  c = (int)(j % 160);
            const float x = (c < 135) ? input[r * 135 + c] : 0.f;
            __half h, l; f16split(x, h, l);
            h0[j] = h; h1[j] = l;
        }
        break;
    }
    case 11: {
        for (long j = tid0; j < 6L * 2 * 512; j += strd) stats[j] = 0.0f;
        for (long j = tid0; j < 512; j += strd) cnt[j] = 0;
        if (tid0 == 0) { loss[0] = 0.0f; ((int*)loss)[1] = 0; }
        for (long k = tid0; k < 512; k += strd) {
            float s = 0.f;
            for (int d = 0; d < 512; ++d) {
                const float v = cb[k * 512 + d];
                s += v * v;
            }
            cn[k] = s;
        }
        break;
    }
    }
}

// ======================= BN normalize (+ReLU), 4-wide, smem LUT =============
__global__ void bn_norm2(const float* __restrict__ X,
                         const float* __restrict__ gamma, const float* __restrict__ beta,
                         const float* __restrict__ gsum, const float* __restrict__ gssq,
                         int M, __half* __restrict__ h0, __half* __restrict__ h1)
{
    __shared__ float s_scale[512], s_shift[512];
    const float invM = 1.0f / (float)M;
    for (int c = threadIdx.x; c < 512; c += blockDim.x) {
        const float mn = gsum[c] * invM;
        const float vr = gssq[c] * invM - mn * mn;
        const float sc = rsqrtf(vr + EPSV) * gamma[c];
        s_scale[c] = sc;
        s_shift[c] = beta[c] - mn * sc;
    }
    __syncthreads();

    const int total4 = (M * 512) >> 2;
    for (int i4 = blockIdx.x * blockDim.x + threadIdx.x; i4 < total4;
         i4 += gridDim.x * blockDim.x) {
        const long i = (long)i4 << 2;
        const int c0 = (int)(i & 511);
        const float4 x = *(const float4*)&X[i];
        const float v[4] = {x.x, x.y, x.z, x.w};
        __half hh[4], ll[4];
        #pragma unroll
        for (int j = 0; j < 4; ++j) {
            float y = fmaf(v[j], s_scale[c0 + j], s_shift[c0 + j]);
            y = y > 0.0f ? y : 0.0f;
            f16split(y, hh[j], ll[j]);
        }
        *(__half2*)&h0[i]     = __halves2half2(hh[0], hh[1]);
        *(__half2*)&h0[i + 2] = __halves2half2(hh[2], hh[3]);
        *(__half2*)&h1[i]     = __halves2half2(ll[0], ll[1]);
        *(__half2*)&h1[i + 2] = __halves2half2(ll[2], ll[3]);
    }
}

// ======================= vector quantization + finalize =====================
// argmin + split-f16 q copy + counts + loss; z-norm inline; the LAST block
// (atomic ticket) computes vq_loss/perplexity scalars.
__global__ void vq_argmin(const float* __restrict__ scores, const float* __restrict__ cnorm,
                          const float* __restrict__ cb,
                          const __half* __restrict__ cb0, const __half* __restrict__ cb1,
                          const float* __restrict__ zr,
                          const float* __restrict__ zsum, const float* __restrict__ zssq,
                          const float* __restrict__ zg, const float* __restrict__ zb,
                          __half* __restrict__ qh, __half* __restrict__ ql,
                          int* __restrict__ counts, float* __restrict__ loss,
                          float* __restrict__ out, long outsize)
{
    const int n = blockIdx.x;
    const int k = threadIdx.x;
    const float d = cnorm[k] - 2.0f * scores[(long)n * 512 + k];
    __shared__ float sv[512];
    __shared__ int   si[512];
    __shared__ int   is_last;
    sv[k] = d; si[k] = k;
    __syncthreads();
    for (int st = 256; st > 0; st >>= 1) {
        if (k < st) {
            const float ov = sv[k + st];
            const int   oi = si[k + st];
            if (ov < sv[k] || (ov == sv[k] && oi < si[k])) { sv[k] = ov; si[k] = oi; }
        }
        __syncthreads();
    }
    const int best = si[0];
    __syncthreads();

    qh[(long)n * 512 + k] = cb0[(long)best * 512 + k];
    ql[(long)n * 512 + k] = cb1[(long)best * 512 + k];

    const float invM = 1.0f / 1024.0f;
    const float mn = zsum[k] * invM;
    const float vr = zssq[k] * invM - mn * mn;
    const float sc = rsqrtf(vr + EPSV) * zg[k];
    float zn = fmaf(zr[(long)n * 512 + k], sc, zb[k] - mn * sc);
    zn = zn > 0.f ? zn : 0.f;

    const float diff = cb[(long)best * 512 + k] - zn;
    sv[k] = diff * diff;
    __syncthreads();
    for (int st = 256; st > 0; st >>= 1) {
        if (k < st) sv[k] += sv[k + st];
        __syncthreads();
    }
    if (k == 0) {
        atomicAdd(&counts[best], 1);
        atomicAdd(loss, sv[0]);
    }

    // ---- last-block finalize ----
    __threadfence();
    if (k == 0) {
        int* tick = (int*)loss + 1;
        const int old = atomicAdd(tick, 1);
        is_last = (old == (int)gridDim.x - 1);
    }
    __syncthreads();
    if (is_last) {
        const float p = (float)counts[k] * (1.0f / 1024.0f);
        sv[k] = p * logf(p + 1e-10f);
        __syncthreads();
        for (int st = 256; st > 0; st >>= 1) {
            if (k < st) sv[k] += sv[k + st];
            __syncthreads();
        }
        if (k == 0) {
            const long R = 1024L * 30 * 135;
            if (outsize >= R + 2) {
                out[R]     = loss[0] * 1.25f / (1024.0f * 512.0f);
                out[R + 1] = expf(-sv[0]);
            }
        }
    }
}

// ======================= host launch ========================================
static inline dim3 grid128(int M, int N) { return dim3((N + 127) / 128, (M + 127) / 128); }
static inline dim3 grid6464(int M, int N) { return dim3((N + 63) / 64, (M + 63) / 64); }

extern "C" void kernel_launch(void* const* d_in, const int* in_sizes, int n_in,
                              void* d_out, int out_size)
{
    (void)in_sizes; (void)n_in;
    float* buf = nullptr;
    __half* hb = nullptr;
    cudaGetSymbolAddress((void**)&buf, g_buf);
    cudaGetSymbolAddress((void**)&hb, g_hbuf);
    cudaFuncSetAttribute((const void*)gemm_hh<2,2>, cudaFuncAttributeMaxDynamicSharedMemorySize, DS22);
    cudaFuncSetAttribute((const void*)gemm_hh<1,1>, cudaFuncAttributeMaxDynamicSharedMemorySize, DS11);

    const float* input = (const float*)d_in[0];
    const float* W_in  = (const float*)d_in[1];
    const float* b_in  = (const float*)d_in[2];
    const float* w_e1  = (const float*)d_in[3];
    const float* g_e1  = (const float*)d_in[4];
    const float* b_e1  = (const float*)d_in[5];
    const float* w_e2  = (const float*)d_in[6];
    const float* g_e2  = (const float*)d_in[7];
    const float* b_e2  = (const float*)d_in[8];
    const float* w_e3  = (const float*)d_in[9];
    const float* g_e3  = (const float*)d_in[10];
    const float* b_e3  = (const float*)d_in[11];
    const float* cb    = (const float*)d_in[12];
    const float* W_q   = (const float*)d_in[13];
    const float* b_q   = (const float*)d_in[14];
    const float* w_d1  = (const float*)d_in[15];
    const float* g_d1  = (const float*)d_in[16];
    const float* b_d1  = (const float*)d_in[17];
    const float* w_d2  = (const float*)d_in[18];
    const float* g_d2  = (const float*)d_in[19];
    const float* b_d2  = (const float*)d_in[20];
    const float* w_d3  = (const float*)d_in[21];
    const float* g_d3  = (const float*)d_in[22];
    const float* b_d3  = (const float*)d_in[23];
    const float* W_out = (const float*)d_in[24];
    const float* b_out = (const float*)d_in[25];

    float* e1r  = buf + O_E1R;
    float* e2r  = buf + O_E2R;
    float* zr   = buf + O_ZR;
    float* d1r  = buf + O_D1R;
    float* d2r  = buf + O_D2R;
    float* d3r  = buf + O_D3R;
    float* sc   = buf + O_SC;
    float* cn   = buf + O_CN;
    float* stats= buf + O_STAT;
    float* loss = buf + O_LOSS;
    int*   cnt  = (int*)(buf + O_CNT);

    __half* we1_0 = hb + H_WE1; __half* we1_1 = we1_0 + 512L * 2560;
    __half* we2_0 = hb + H_WE2; __half* we2_1 = we2_0 + 512L * 1536;
    __half* we3_0 = hb + H_WE3; __half* we3_1 = we3_0 + 512L * 1024;
    __half* wd1_0 = hb + H_WD1; __half* wd1_1 = wd1_0 + 1024L * 512;
    __half* wd2_0 = hb + H_WD2; __half* wd2_1 = wd2_0 + 1536L * 512;
    __half* wd3_0 = hb + H_WD3; __half* wd3_1 = wd3_0 + 2560L * 512;
    __half* wit_0 = hb + H_WIT; __half* wit_1 = wit_0 + 512L * 160;
    __half* wqt_0 = hb + H_WQT; __half* wqt_1 = wqt_0 + 512L * 512;
    __half* wot_0 = hb + H_WOT; __half* wot_1 = wot_0 + 135L * 512;
    __half* cb_0  = hb + H_CB;  __half* cb_1  = cb_0  + 512L * 512;
    __half* xin_0 = hb + H_XIN; __half* xin_1 = xin_0 + 30720L * 160;
    __half* x0_0  = hb + H_X0;  __half* x0_1  = x0_0  + 30720L * 512;
    __half* e1_0  = hb + H_E1;  __half* e1_1  = e1_0  + 6144L * 512;
    __half* e2_0  = hb + H_E2;  __half* e2_1  = e2_0  + 2048L * 512;
    __half* z_0   = hb + H_Z;   __half* z_1   = z_0   + 1024L * 512;
    __half* q_0   = hb + H_Q;   __half* q_1   = q_0   + 1024L * 512;
    __half* d0_0  = hb + H_D0;  __half* d0_1  = d0_0  + 1024L * 512;
    __half* d1_0  = hb + H_D1;  __half* d1_1  = d1_0  + 1024L * 1024;
    __half* d2_0  = hb + H_D2;  __half* d2_1  = d2_0  + 2048L * 1536;
    __half* d3_0  = hb + H_D3;  __half* d3_1  = d3_0  + 30720L * 512;

    float* out = (float*)d_out;

    // ---- prep: everything in ONE launch ----
    prep_all<<<dim3(160, 12), 256>>>(w_e1, w_e2, w_e3, w_d1, w_d2, w_d3,
                                     W_in, W_q, W_out, cb, input,
                                     hb, cn, stats, loss, cnt);

    float* st0 = stats;
    float* st1 = stats + 1024;
    float* st2 = stats + 2048;
    float* st3 = stats + 3072;
    float* st4 = stats + 4096;
    float* st5 = stats + 5120;

    // ---- input GEMM: K=135(pad160) -> 512, split-only out, perm ----
    gemm_hh<2,2><<<grid128(30720, 512), 256, DS22>>>(
        xin_0, xin_1, wit_0, wit_1, b_in, nullptr, x0_0, x0_1,
        nullptr, nullptr, 30720, 512, 160, 1);

    // ---- encoder ----
    gemm_hh<2,2><<<grid128(6144, 512), 256, DS22>>>(
        x0_0, x0_1, we1_0, we1_1, nullptr, e1r, nullptr, nullptr,
        st0, st0 + 512, 6144, 512, 2560, 0);
    bn_norm2<<<2048, 256>>>(e1r, g_e1, b_e1, st0, st0 + 512, 6144, e1_0, e1_1);

    gemm_hh<1,1><<<grid6464(2048, 512), 256, DS11>>>(
        e1_0, e1_1, we2_0, we2_1, nullptr, e2r, nullptr, nullptr,
        st1, st1 + 512, 2048, 512, 1536, 0);
    bn_norm2<<<1024, 256>>>(e2r, g_e2, b_e2, st1, st1 + 512, 2048, e2_0, e2_1);

    gemm_hh<1,1><<<grid6464(1024, 512), 256, DS11>>>(
        e2_0, e2_1, we3_0, we3_1, nullptr, zr, nullptr, nullptr,
        st2, st2 + 512, 1024, 512, 1024, 0);
    bn_norm2<<<512, 256>>>(zr, g_e3, b_e3, st2, st2 + 512, 1024, z_0, z_1);

    // ---- vector quantization (finalize folded in) ----
    gemm_hh<1,1><<<grid6464(1024, 512), 256, DS11>>>(
        z_0, z_1, cb_0, cb_1, nullptr, sc, nullptr, nullptr,
        nullptr, nullptr, 1024, 512, 512, 0);
    vq_argmin<<<1024, 512>>>(sc, cn, cb, cb_0, cb_1,
                             zr, st2, st2 + 512, g_e3, b_e3,
                             q_0, q_1, cnt, loss, out, (long)out_size);

    // ---- decoder ----
    gemm_hh<1,1><<<grid6464(1024, 512), 256, DS11>>>(
        q_0, q_1, wqt_0, wqt_1, b_q, nullptr, d0_0, d0_1,
        nullptr, nullptr, 1024, 512, 512, 0);

    gemm_hh<1,1><<<grid6464(1024, 1024), 256, DS11>>>(
        d0_0, d0_1, wd1_0, wd1_1, nullptr, d1r, nullptr, nullptr,
        st3, st3 + 512, 1024, 1024, 512, 0);
    bn_norm2<<<1024, 256>>>(d1r, g_d1, b_d1, st3, st3 + 512, 2048, d1_0, d1_1);

    gemm_hh<2,2><<<grid128(2048, 1536), 256, DS22>>>(
        d1_0, d1_1, wd2_0, wd2_1, nullptr, d2r, nullptr, nullptr,
        st4, st4 + 512, 2048, 1536, 512, 0);
    bn_norm2<<<2048, 256>>>(d2r, g_d2, b_d2, st4, st4 + 512, 6144, d2_0, d2_1);

    gemm_hh<2,2><<<grid128(6144, 2560), 256, DS22>>>(
        d2_0, d2_1, wd3_0, wd3_1, nullptr, d3r, nullptr, nullptr,
        st5, st5 + 512, 6144, 2560, 512, 0);
    bn_norm2<<<2048, 256>>>(d3r, g_d3, b_d3, st5, st5 + 512, 30720, d3_0, d3_1);

    // ---- output GEMM -> recon ----
    gemm_hh<2,2><<<grid128(30720, 135), 256, DS22>>>(
        d3_0, d3_1, wot_0, wot_1, b_out, out, nullptr, nullptr,
        nullptr, nullptr, 30720, 135, 512, 0);
}

// round 16
// speedup vs baseline: 1.1055x; 1.0508x over previous
#include <cuda_runtime.h>
#include <cuda_fp16.h>
#include <math.h>
#include <stdint.h>

// ---------------------------------------------------------------------------
// VQ-VAE forward. T=30, B=1024, D_POSE=135, H=512, K_CODES=512.
// Row-major GEMMs C[M,N] = A[M,K] * B'[N,K]^T, mma.sync.m16n8k16 f16,
// 3xFP16 hi/lo split (err ~2^-24). Pre-split f16 operands; mainloop pure
// cp.async + ldmatrix + mma; 3-stage pipeline, ONE syncthreads per chunk;
// 64B swizzled rows; 2 CTAs/SM. BN stats in producer epilogues; normalize
// as separate pass (A-fusion measured slower, R12/R13).
// R16: per-layer tile shapes for wave balance — e1/d2 use 64x128 tiles
// (grid 384 vs 192 -> makespan 6 vs 8 units); small GEMMs 64x64; big 128x128.
// ---------------------------------------------------------------------------

#define EPSV 1e-5f

// ======================= fp32 scratch ======================================
constexpr long O_E1R = 0;                        // 6144 x 512 (raw, pre-BN)
constexpr long O_E2R = O_E1R + 6144L * 512;      // 2048 x 512
constexpr long O_ZR  = O_E2R + 2048L * 512;      // 1024 x 512
constexpr long O_D1R = O_ZR  + 1024L * 512;      // 1024 x 1024
constexpr long O_D2R = O_D1R + 1024L * 1024;     // 2048 x 1536
constexpr long O_D3R = O_D2R + 2048L * 1536;     // 6144 x 2560
constexpr long O_SC  = O_D3R + 6144L * 2560;     // 1024 x 512
constexpr long O_CN  = O_SC  + 1024L * 512;      // 512
constexpr long O_STAT= O_CN  + 512;              // 6 x 2 x 512
constexpr long O_LOSS= O_STAT+ 6L * 2 * 512;     // [0]=loss, [1]=ticket(int)
constexpr long O_CNT = O_LOSS+ 512;
constexpr long TOTALF= O_CNT + 512;

__device__ float g_buf[TOTALF];

// ======================= f16 split scratch (hi then lo per buffer) =========
constexpr long H_WE1 = 0;                          // [512,2560]
constexpr long H_WE2 = H_WE1 + 2L * 512 * 2560;    // [512,1536]
constexpr long H_WE3 = H_WE2 + 2L * 512 * 1536;    // [512,1024]
constexpr long H_WD1 = H_WE3 + 2L * 512 * 1024;    // [1024,512]
constexpr long H_WD2 = H_WD1 + 2L * 1024 * 512;    // [1536,512]
constexpr long H_WD3 = H_WD2 + 2L * 1536 * 512;    // [2560,512]
constexpr long H_WIT = H_WD3 + 2L * 2560 * 512;    // [512,160]
constexpr long H_WQT = H_WIT + 2L * 512 * 160;     // [512,512]
constexpr long H_WOT = H_WQT + 2L * 512 * 512;     // [135,512]
constexpr long H_CB  = H_WOT + 2L * 135 * 512;     // [512,512]
constexpr long H_XIN = H_CB  + 2L * 512 * 512;     // [30720,160]
constexpr long H_X0  = H_XIN + 2L * 30720 * 160;   // [30720,512]
constexpr long H_E1  = H_X0  + 2L * 30720 * 512;   // [6144,512]
constexpr long H_E2  = H_E1  + 2L * 6144 * 512;    // [2048,512]
constexpr long H_Z   = H_E2  + 2L * 2048 * 512;    // [1024,512]
constexpr long H_Q   = H_Z   + 2L * 1024 * 512;    // [1024,512]
constexpr long H_D0  = H_Q   + 2L * 1024 * 512;    // [1024,512]
constexpr long H_D1  = H_D0  + 2L * 1024 * 512;    // [1024,1024]
constexpr long H_D2  = H_D1  + 2L * 1024 * 1024;   // [2048,1536]
constexpr long H_D3  = H_D2  + 2L * 2048 * 1536;   // [30720,512]
constexpr long TOTALH= H_D3  + 2L * 30720 * 512;

__device__ __half g_hbuf[TOTALH];

// ======================= helpers ===========================================
__device__ __forceinline__ uint32_t smem_u32(const void* p)
{
    return (uint32_t)__cvta_generic_to_shared(p);
}

__device__ __forceinline__ void f16split(float x, __half& h, __half& l)
{
    h = __float2half_rn(x);
    l = __float2half_rn(x - __half2float(h));
}

__device__ __forceinline__ void mma_f16(float* c, const uint32_t* a, const uint32_t* b)
{
    asm volatile(
        "mma.sync.aligned.m16n8k16.row.col.f32.f16.f16.f32 "
        "{%0,%1,%2,%3}, {%4,%5,%6,%7}, {%8,%9}, {%0,%1,%2,%3};"
        : "+f"(c[0]), "+f"(c[1]), "+f"(c[2]), "+f"(c[3])
        : "r"(a[0]), "r"(a[1]), "r"(a[2]), "r"(a[3]), "r"(b[0]), "r"(b[1]));
}

__device__ __forceinline__ void ldm4(uint32_t& r0, uint32_t& r1, uint32_t& r2,
                                     uint32_t& r3, uint32_t addr)
{
    asm volatile("ldmatrix.sync.aligned.m8n8.x4.shared.b16 {%0,%1,%2,%3}, [%4];"
                 : "=r"(r0), "=r"(r1), "=r"(r2), "=r"(r3) : "r"(addr));
}

__device__ __forceinline__ void cp16(uint32_t dst, const void* src, int pred)
{
    asm volatile("cp.async.cg.shared.global [%0], [%1], 16, %2;"
                 :: "r"(dst), "l"(src), "r"(pred ? 16 : 0) : "memory");
}
__device__ __forceinline__ void cp_commit()
{
    asm volatile("cp.async.commit_group;" ::: "memory");
}

// 64B rows, chunk swizzle: byte = row*64 + ((ch ^ ((row>>1)&3)) * 16)
__device__ __forceinline__ uint32_t swz(int row, int ch)
{
    return (uint32_t)(row * 64 + ((ch ^ ((row >> 1) & 3)) << 4));
}

// ======================= GEMM ==============================================
// CTA tile (64*MTILES) x (64*NTILES), BK=32 halves, 256 threads, 8 warps
// (4M x 2N), warp tile (16*MTILES) x (32*NTILES). 3-stage cp.async pipeline
// with ONE __syncthreads per chunk (wait -> sync -> issue next -> compute).
// 2 CTAs/SM. Inactive N-edge warps skip MMA work.

template<int MTILES, int NTILES>
__global__ __launch_bounds__(256, 2)
void gemm_hh(const __half* __restrict__ A0, const __half* __restrict__ A1,
             const __half* __restrict__ B0, const __half* __restrict__ B1,
             const float* __restrict__ bias, float* __restrict__ Cf,
             __half* __restrict__ C0, __half* __restrict__ C1,
             float* __restrict__ gsum, float* __restrict__ gssq,
             int M, int N, int Kp, int perm)
{
    constexpr int AROWS   = 64 * MTILES;
    constexpr int BROWS   = 64 * NTILES;
    constexpr int NT      = 4 * NTILES;          // n-subtiles per warp
    constexpr int OFF_A1_ = AROWS * 64;
    constexpr int OFF_B0_ = 2 * AROWS * 64;
    constexpr int OFF_B1_ = OFF_B0_ + BROWS * 64;
    constexpr int STG     = OFF_B0_ + 2 * BROWS * 64;

    extern __shared__ char dsm[];
    const uint32_t dynb = smem_u32(dsm);
    const uint32_t base = (dynb + 1023u) & ~1023u;
    char* smg = dsm + (base - dynb);

    const int tid  = threadIdx.x;
    const int wid  = tid >> 5;
    const int lane = tid & 31;
    const int wm   = (wid & 3) * (16 * MTILES);
    const int wn   = (wid >> 2) * (32 * NTILES);
    const int g    = lane >> 2;
    const int t    = lane & 3;
    const int m0   = blockIdx.y * AROWS;
    const int n0   = blockIdx.x * BROWS;
    const bool wactive = (n0 + wn) < N;

    const int nk = Kp >> 5;

    auto issue = [&](int k0, uint32_t stg) {
        #pragma unroll
        for (int i = 0; i < MTILES; ++i) {
            const int slot = tid + i * 256;
            const int row = slot >> 2, ch = slot & 3;
            const int gm = m0 + row;
            const int ok = gm < M;
            const long off = (long)(ok ? gm : 0) * Kp + ch * 8 + k0;
            const uint32_t d = swz(row, ch);
            cp16(stg + 0       + d, A0 + off, ok);
            cp16(stg + OFF_A1_ + d, A1 + off, ok);
        }
        #pragma unroll
        for (int i = 0; i < NTILES; ++i) {
            const int slot = tid + i * 256;
            const int row = slot >> 2, ch = slot & 3;
            const int gn = n0 + row;
            const int ok = gn < N;
            const long off = (long)(ok ? gn : 0) * Kp + ch * 8 + k0;
            const uint32_t d = swz(row, ch);
            cp16(stg + OFF_B0_ + d, B0 + off, ok);
            cp16(stg + OFF_B1_ + d, B1 + off, ok);
        }
        cp_commit();
    };

    float acc[MTILES][NT][4];
    #pragma unroll
    for (int a = 0; a < MTILES; a++)
        #pragma unroll
        for (int b = 0; b < NT; b++)
            #pragma unroll
            for (int c = 0; c < 4; c++) acc[a][b][c] = 0.f;

    // prefill two stages
    issue(0, base);
    if (nk > 1) issue(32, base + STG);

    for (int it = 0; it < nk; ++it) {
        const uint32_t stg_u = base + (uint32_t)(it % 3) * STG;

        // wait for stage 'it' (pending: it [, it+1]) then ONE barrier
        if (it + 1 < nk) {
            asm volatile("cp.async.wait_group 1;" ::: "memory");
        } else {
            asm volatile("cp.async.wait_group 0;" ::: "memory");
        }
        __syncthreads();

        // issue stage it+2 (writes stage (it-1)%3; its readers finished
        // before the barrier above)
        if (it + 2 < nk)
            issue((it + 2) << 5, base + (uint32_t)((it + 2) % 3) * STG);

        if (wactive) {
            #pragma unroll
            for (int ks = 0; ks < 2; ++ks) {
                uint32_t aH[MTILES][4], aL[MTILES][4];
                {
                    const int arw = (lane & 15);
                    const int cA  = ks * 2 + (lane >> 4);
                    #pragma unroll
                    for (int mt = 0; mt < MTILES; ++mt) {
                        const int row = wm + mt * 16 + arw;
                        const uint32_t ad = stg_u + swz(row, cA);
                        ldm4(aH[mt][0], aH[mt][1], aH[mt][2], aH[mt][3], ad + 0);
                        ldm4(aL[mt][0], aL[mt][1], aL[mt][2], aL[mt][3], ad + OFF_A1_);
                    }
                }
                const int brw = (lane >> 4) * 8 + (lane & 7);
                const int cB  = ks * 2 + ((lane >> 3) & 1);
                #pragma unroll
                for (int p = 0; p < 2 * NTILES; ++p) {
                    uint32_t bH[4], bL[4];
                    const int row = wn + p * 16 + brw;
                    const uint32_t bd = stg_u + swz(row, cB);
                    ldm4(bH[0], bH[1], bH[2], bH[3], bd + OFF_B0_);
                    ldm4(bL[0], bL[1], bL[2], bL[3], bd + OFF_B1_);
                    #pragma unroll
                    for (int sub = 0; sub < 2; ++sub) {
                        const int nt = 2 * p + sub;
                        uint32_t b_h[2] = {bH[sub * 2], bH[sub * 2 + 1]};
                        uint32_t b_l[2] = {bL[sub * 2], bL[sub * 2 + 1]};
                        #pragma unroll
                        for (int mt = 0; mt < MTILES; ++mt) {
                            mma_f16(acc[mt][nt], aH[mt], b_h);
                            mma_f16(acc[mt][nt], aH[mt], b_l);
                            mma_f16(acc[mt][nt], aL[mt], b_h);
                        }
                    }
                }
            }
        }
    }
    __syncthreads();   // protect smem reuse by epilogue stats area

    // ---- epilogue: stores ----
    const bool neven = ((N & 1) == 0);
    if (wactive) {
        #pragma unroll
        for (int mt = 0; mt < MTILES; ++mt) {
            #pragma unroll
            for (int half = 0; half < 2; ++half) {
                const int gm = m0 + wm + mt * 16 + g + half * 8;
                if (gm >= M) continue;
                const int orow = perm ? ((gm & 1023) * 30 + (gm >> 10)) : gm;
                #pragma unroll
                for (int nt = 0; nt < NT; ++nt) {
                    const int col = n0 + wn + nt * 8 + t * 2;
                    if (col >= N) continue;
                    float v0 = acc[mt][nt][half * 2 + 0];
                    float v1 = acc[mt][nt][half * 2 + 1];
                    if (bias) {
                        v0 += bias[col];
                        if (col + 1 < N) v1 += bias[col + 1];
                    }
                    if (Cf) {
                        if (neven && col + 1 < N) {
                            *(float2*)&Cf[(long)orow * N + col] = make_float2(v0, v1);
                        } else {
                            Cf[(long)orow * N + col] = v0;
                            if (col + 1 < N) Cf[(long)orow * N + col + 1] = v1;
                        }
                    }
                    if (C0 && neven && col + 1 < N) {
                        __half h0, l0, h1, l1;
                        f16split(v0, h0, l0);
                        f16split(v1, h1, l1);
                        *(__half2*)&C0[(long)orow * N + col] = __halves2half2(h0, h1);
                        *(__half2*)&C1[(long)orow * N + col] = __halves2half2(l0, l1);
                    }
                }
            }
        }
    }

    // ---- fused BN stats (raw accumulators; bias null for these layers) ----
    if (gsum) {
        float* ssum = (float*)smg;          // [BROWS]
        float* ssq2 = ssum + BROWS;         // [BROWS]
        if (tid < 2 * BROWS) ((float*)smg)[tid] = 0.0f;
        __syncthreads();
        if (wactive) {
            #pragma unroll
            for (int nt = 0; nt < NT; ++nt) {
                #pragma unroll
                for (int j = 0; j < 2; ++j) {
                    float s = 0.f, s2 = 0.f;
                    #pragma unroll
                    for (int mt = 0; mt < MTILES; ++mt) {
                        #pragma unroll
                        for (int half = 0; half < 2; ++half) {
                            const float v = acc[mt][nt][half * 2 + j];
                            s += v; s2 += v * v;
                        }
                    }
                    #pragma unroll
                    for (int o = 16; o >= 4; o >>= 1) {
                        s  += __shfl_down_sync(0xffffffffu, s,  o);
                        s2 += __shfl_down_sync(0xffffffffu, s2, o);
                    }
                    if (g == 0) {
                        const int cl = wn + nt * 8 + t * 2 + j;
                        atomicAdd(&ssum[cl], s);
                        atomicAdd(&ssq2[cl], s2);
                    }
                }
            }
        }
        __syncthreads();
        if (tid < BROWS && n0 + tid < N) {
            atomicAdd(&gsum[(n0 + tid) & 511], ssum[tid]);
            atomicAdd(&gssq[(n0 + tid) & 511], ssq2[tid]);
        }
    }
}

constexpr int DS22 = 3 * (2 * 128 * 64 + 2 * 128 * 64) + 1024;   // 99328
constexpr int DS12 = 3 * (2 * 64 * 64 + 2 * 128 * 64) + 1024;    // 74752
constexpr int DS11 = 3 * (2 * 64 * 64 + 2 * 64 * 64) + 1024;     // 50176

// ======================= single prep kernel ================================
__global__ void prep_all(const float* __restrict__ w_e1, const float* __restrict__ w_e2,
                         const float* __restrict__ w_e3, const float* __restrict__ w_d1,
                         const float* __restrict__ w_d2, const float* __restrict__ w_d3,
                         const float* __restrict__ W_in, const float* __restrict__ W_q,
                         const float* __restrict__ W_out, const float* __restrict__ cb,
                         const float* __restrict__ input,
                         __half* hb, float* cn, float* stats, float* loss, int* cnt)
{
    const int  job = blockIdx.y;
    const long tid0 = (long)blockIdx.x * blockDim.x + threadIdx.x;
    const long strd = (long)gridDim.x * blockDim.x;

    auto enc = [&](const float* w, __half* h0, __half* h1, int Kk, int Kp) {
        const int I = 512, Ke = I * Kk;
        const long n = 512L * Kp;
        for (long j = tid0; j < n; j += strd) {
            const int o  = (int)(j / Kp);
            const int kk = (int)(j % Kp);
            float x = 0.f;
            if (kk < Ke) x = w[(long)o * Ke + (long)(kk % I) * Kk + (kk / I)];
            __half h, l; f16split(x, h, l);
            h0[j] = h; h1[j] = l;
        }
    };
    auto dec = [&](const float* w, __half* h0, __half* h1, int Kk) {
        const int I = 512, O = 512;
        const long n = (long)Kk * O * I;
        for (long j = tid0; j < n; j += strd) {
            const int i  = (int)(j % I);
            const int nn = (int)(j / I);
            const int o  = nn % O;
            const int k  = nn / O;
            const float x = w[(long)i * O * Kk + (long)o * Kk + k];
            __half h, l; f16split(x, h, l);
            h0[j] = h; h1[j] = l;
        }
    };
    auto tr = [&](const float* in, __half* h0, __half* h1, int R, int C, int Kp) {
        const long n = (long)C * Kp;
        for (long j = tid0; j < n; j += strd) {
            const int c = (int)(j / Kp);
            const int r = (int)(j % Kp);
            const float x = (r < R) ? in[(long)r * C + c] : 0.f;
            __half h, l; f16split(x, h, l);
            h0[j] = h; h1[j] = l;
        }
    };

    switch (job) {
    case 0: enc(w_e1, hb + H_WE1, hb + H_WE1 + 512L * 2560, 5, 2560); break;
    case 1: enc(w_e2, hb + H_WE2, hb + H_WE2 + 512L * 1536, 3, 1536); break;
    case 2: enc(w_e3, hb + H_WE3, hb + H_WE3 + 512L * 1024, 2, 1024); break;
    case 3: dec(w_d1, hb + H_WD1, hb + H_WD1 + 1024L * 512, 2); break;
    case 4: dec(w_d2, hb + H_WD2, hb + H_WD2 + 1536L * 512, 3); break;
    case 5: dec(w_d3, hb + H_WD3, hb + H_WD3 + 2560L * 512, 5); break;
    case 6: tr(W_in,  hb + H_WIT, hb + H_WIT + 512L * 160, 135, 512, 160); break;
    case 7: tr(W_q,   hb + H_WQT, hb + H_WQT + 512L * 512, 512, 512, 512); break;
    case 8: tr(W_out, hb + H_WOT, hb + H_WOT + 135L * 512, 512, 135, 512); break;
    case 9: {
        __half* h0 = hb + H_CB; __half* h1 = h0 + 512L * 512;
        for (long j = tid0; j < 512L * 512; j += strd) {
            __half h, l; f16split(cb[j], h, l);
            h0[j] = h; h1[j] = l;
        }
        break;
    }
    case 10: {
        __half* h0 = hb + H_XIN; __half* h1 = h0 + 30720L * 160;
        const long n = 30720L * 160;
        for (long j = tid0; j < n; j += strd) {
            const long r = j / 160;
            const int  c = (int)(j % 160);
            const float x = (c < 135) ? input[r * 135 + c] : 0.f;
            __half h, l; f16split(x, h, l);
            h0[j] = h; h1[j] = l;
        }
        break;
    }
    case 11: {
        for (long j = tid0; j < 6L * 2 * 512; j += strd) stats[j] = 0.0f;
        for (long j = tid0; j < 512; j += strd) cnt[j] = 0;
        if (tid0 == 0) { loss[0] = 0.0f; ((int*)loss)[1] = 0; }
        for (long k = tid0; k < 512; k += strd) {
            float s = 0.f;
            for (int d = 0; d < 512; ++d) {
                const float v = cb[k * 512 + d];
                s += v * v;
            }
            cn[k] = s;
        }
        break;
    }
    }
}

// ======================= BN normalize (+ReLU), 4-wide, smem LUT =============
__global__ void bn_norm2(const float* __restrict__ X,
                         const float* __restrict__ gamma, const float* __restrict__ beta,
                         const float* __restrict__ gsum, const float* __restrict__ gssq,
                         int M, __half* __restrict__ h0, __half* __restrict__ h1)
{
    __shared__ float s_scale[512], s_shift[512];
    const float invM = 1.0f / (float)M;
    for (int c = threadIdx.x; c < 512; c += blockDim.x) {
        const float mn = gsum[c] * invM;
        const float vr = gssq[c] * invM - mn * mn;
        const float sc = rsqrtf(vr + EPSV) * gamma[c];
        s_scale[c] = sc;
        s_shift[c] = beta[c] - mn * sc;
    }
    __syncthreads();

    const int total4 = (M * 512) >> 2;
    for (int i4 = blockIdx.x * blockDim.x + threadIdx.x; i4 < total4;
         i4 += gridDim.x * blockDim.x) {
        const long i = (long)i4 << 2;
        const int c0 = (int)(i & 511);
        const float4 x = *(const float4*)&X[i];
        const float v[4] = {x.x, x.y, x.z, x.w};
        __half hh[4], ll[4];
        #pragma unroll
        for (int j = 0; j < 4; ++j) {
            float y = fmaf(v[j], s_scale[c0 + j], s_shift[c0 + j]);
            y = y > 0.0f ? y : 0.0f;
            f16split(y, hh[j], ll[j]);
        }
        *(__half2*)&h0[i]     = __halves2half2(hh[0], hh[1]);
        *(__half2*)&h0[i + 2] = __halves2half2(hh[2], hh[3]);
        *(__half2*)&h1[i]     = __halves2half2(ll[0], ll[1]);
        *(__half2*)&h1[i + 2] = __halves2half2(ll[2], ll[3]);
    }
}

// ======================= vector quantization + finalize =====================
__global__ void vq_argmin(const float* __restrict__ scores, const float* __restrict__ cnorm,
                          const float* __restrict__ cb,
                          const __half* __restrict__ cb0, const __half* __restrict__ cb1,
                          const float* __restrict__ zr,
                          const float* __restrict__ zsum, const float* __restrict__ zssq,
                          const float* __restrict__ zg, const float* __restrict__ zb,
                          __half* __restrict__ qh, __half* __restrict__ ql,
                          int* __restrict__ counts, float* __restrict__ loss,
                          float* __restrict__ out, long outsize)
{
    const int n = blockIdx.x;
    const int k = threadIdx.x;
    const float d = cnorm[k] - 2.0f * scores[(long)n * 512 + k];
    __shared__ float sv[512];
    __shared__ int   si[512];
    __shared__ int   is_last;
    sv[k] = d; si[k] = k;
    __syncthreads();
    for (int st = 256; st > 0; st >>= 1) {
        if (k < st) {
            const float ov = sv[k + st];
            const int   oi = si[k + st];
            if (ov < sv[k] || (ov == sv[k] && oi < si[k])) { sv[k] = ov; si[k] = oi; }
        }
        __syncthreads();
    }
    const int best = si[0];
    __syncthreads();

    qh[(long)n * 512 + k] = cb0[(long)best * 512 + k];
    ql[(long)n * 512 + k] = cb1[(long)best * 512 + k];

    const float invM = 1.0f / 1024.0f;
    const float mn = zsum[k] * invM;
    const float vr = zssq[k] * invM - mn * mn;
    const float sc = rsqrtf(vr + EPSV) * zg[k];
    float zn = fmaf(zr[(long)n * 512 + k], sc, zb[k] - mn * sc);
    zn = zn > 0.f ? zn : 0.f;

    const float diff = cb[(long)best * 512 + k] - zn;
    sv[k] = diff * diff;
    __syncthreads();
    for (int st = 256; st > 0; st >>= 1) {
        if (k < st) sv[k] += sv[k + st];
        __syncthreads();
    }
    if (k == 0) {
        atomicAdd(&counts[best], 1);
        atomicAdd(loss, sv[0]);
    }

    __threadfence();
    if (k == 0) {
        int* tick = (int*)loss + 1;
        const int old = atomicAdd(tick, 1);
        is_last = (old == (int)gridDim.x - 1);
    }
    __syncthreads();
    if (is_last) {
        const float p = (float)counts[k] * (1.0f / 1024.0f);
        sv[k] = p * logf(p + 1e-10f);
        __syncthreads();
        for (int st = 256; st > 0; st >>= 1) {
            if (k < st) sv[k] += sv[k + st];
            __syncthreads();
        }
        if (k == 0) {
            const long R = 1024L * 30 * 135;
            if (outsize >= R + 2) {
                out[R]     = loss[0] * 1.25f / (1024.0f * 512.0f);
                out[R + 1] = expf(-sv[0]);
            }
        }
    }
}

// ======================= host launch ========================================
static inline dim3 grid128(int M, int N)  { return dim3((N + 127) / 128, (M + 127) / 128); }
static inline dim3 grid64128(int M, int N){ return dim3((N + 127) / 128, (M + 63) / 64); }
static inline dim3 grid6464(int M, int N) { return dim3((N + 63) / 64, (M + 63) / 64); }

extern "C" void kernel_launch(void* const* d_in, const int* in_sizes, int n_in,
                              void* d_out, int out_size)
{
    (void)in_sizes; (void)n_in;
    float* buf = nullptr;
    __half* hb = nullptr;
    cudaGetSymbolAddress((void**)&buf, g_buf);
    cudaGetSymbolAddress((void**)&hb, g_hbuf);
    cudaFuncSetAttribute((const void*)gemm_hh<2,2>, cudaFuncAttributeMaxDynamicSharedMemorySize, DS22);
    cudaFuncSetAttribute((const void*)gemm_hh<1,2>, cudaFuncAttributeMaxDynamicSharedMemorySize, DS12);
    cudaFuncSetAttribute((const void*)gemm_hh<1,1>, cudaFuncAttributeMaxDynamicSharedMemorySize, DS11);

    const float* input = (const float*)d_in[0];
    const float* W_in  = (const float*)d_in[1];
    const float* b_in  = (const float*)d_in[2];
    const float* w_e1  = (const float*)d_in[3];
    const float* g_e1  = (const float*)d_in[4];
    const float* b_e1  = (const float*)d_in[5];
    const float* w_e2  = (const float*)d_in[6];
    const float* g_e2  = (const float*)d_in[7];
    const float* b_e2  = (const float*)d_in[8];
    const float* w_e3  = (const float*)d_in[9];
    const float* g_e3  = (const float*)d_in[10];
    const float* b_e3  = (const float*)d_in[11];
    const float* cb    = (const float*)d_in[12];
    const float* W_q   = (const float*)d_in[13];
    const float* b_q   = (const float*)d_in[14];
    const float* w_d1  = (const float*)d_in[15];
    const float* g_d1  = (const float*)d_in[16];
    const float* b_d1  = (const float*)d_in[17];
    const float* w_d2  = (const float*)d_in[18];
    const float* g_d2  = (const float*)d_in[19];
    const float* b_d2  = (const float*)d_in[20];
    const float* w_d3  = (const float*)d_in[21];
    const float* g_d3  = (const float*)d_in[22];
    const float* b_d3  = (const float*)d_in[23];
    const float* W_out = (const float*)d_in[24];
    const float* b_out = (const float*)d_in[25];

    float* e1r  = buf + O_E1R;
    float* e2r  = buf + O_E2R;
    float* zr   = buf + O_ZR;
    float* d1r  = buf + O_D1R;
    float* d2r  = buf + O_D2R;
    float* d3r  = buf + O_D3R;
    float* sc   = buf + O_SC;
    float* cn   = buf + O_CN;
    float* stats= buf + O_STAT;
    float* loss = buf + O_LOSS;
    int*   cnt  = (int*)(buf + O_CNT);

    __half* we1_0 = hb + H_WE1; __half* we1_1 = we1_0 + 512L * 2560;
    __half* we2_0 = hb + H_WE2; __half* we2_1 = we2_0 + 512L * 1536;
    __half* we3_0 = hb + H_WE3; __half* we3_1 = we3_0 + 512L * 1024;
    __half* wd1_0 = hb + H_WD1; __half* wd1_1 = wd1_0 + 1024L * 512;
    __half* wd2_0 = hb + H_WD2; __half* wd2_1 = wd2_0 + 1536L * 512;
    __half* wd3_0 = hb + H_WD3; __half* wd3_1 = wd3_0 + 2560L * 512;
    __half* wit_0 = hb + H_WIT; __half* wit_1 = wit_0 + 512L * 160;
    __half* wqt_0 = hb + H_WQT; __half* wqt_1 = wqt_0 + 512L * 512;
    __half* wot_0 = hb + H_WOT; __half* wot_1 = wot_0 + 135L * 512;
    __half* cb_0  = hb + H_CB;  __half* cb_1  = cb_0  + 512L * 512;
    __half* xin_0 = hb + H_XIN; __half* xin_1 = xin_0 + 30720L * 160;
    __half* x0_0  = hb + H_X0;  __half* x0_1  = x0_0  + 30720L * 512;
    __half* e1_0  = hb + H_E1;  __half* e1_1  = e1_0  + 6144L * 512;
    __half* e2_0  = hb + H_E2;  __half* e2_1  = e2_0  + 2048L * 512;
    __half* z_0   = hb + H_Z;   __half* z_1   = z_0   + 1024L * 512;
    __half* q_0   = hb + H_Q;   __half* q_1   = q_0   + 1024L * 512;
    __half* d0_0  = hb + H_D0;  __half* d0_1  = d0_0  + 1024L * 512;
    __half* d1_0  = hb + H_D1;  __half* d1_1  = d1_0  + 1024L * 1024;
    __half* d2_0  = hb + H_D2;  __half* d2_1  = d2_0  + 2048L * 1536;
    __half* d3_0  = hb + H_D3;  __half* d3_1  = d3_0  + 30720L * 512;

    float* out = (float*)d_out;

    // ---- prep: everything in ONE launch ----
    prep_all<<<dim3(160, 12), 256>>>(w_e1, w_e2, w_e3, w_d1, w_d2, w_d3,
                                     W_in, W_q, W_out, cb, input,
                                     hb, cn, stats, loss, cnt);

    float* st0 = stats;
    float* st1 = stats + 1024;
    float* st2 = stats + 2048;
    float* st3 = stats + 3072;
    float* st4 = stats + 4096;
    float* st5 = stats + 5120;

    // ---- input GEMM: K=135(pad160) -> 512, split-only out, perm ----
    gemm_hh<2,2><<<grid128(30720, 512), 256, DS22>>>(
        xin_0, xin_1, wit_0, wit_1, b_in, nullptr, x0_0, x0_1,
        nullptr, nullptr, 30720, 512, 160, 1);

    // ---- encoder ----
    // e1: 64x128 tiles -> grid 384 (wave balance; was 192 @128x128)
    gemm_hh<1,2><<<grid64128(6144, 512), 256, DS12>>>(
        x0_0, x0_1, we1_0, we1_1, nullptr, e1r, nullptr, nullptr,
        st0, st0 + 512, 6144, 512, 2560, 0);
    bn_norm2<<<2048, 256>>>(e1r, g_e1, b_e1, st0, st0 + 512, 6144, e1_0, e1_1);

    gemm_hh<1,1><<<grid6464(2048, 512), 256, DS11>>>(
        e1_0, e1_1, we2_0, we2_1, nullptr, e2r, nullptr, nullptr,
        st1, st1 + 512, 2048, 512, 1536, 0);
    bn_norm2<<<1024, 256>>>(e2r, g_e2, b_e2, st1, st1 + 512, 2048, e2_0, e2_1);

    gemm_hh<1,1><<<grid6464(1024, 512), 256, DS11>>>(
        e2_0, e2_1, we3_0, we3_1, nullptr, zr, nullptr, nullptr,
        st2, st2 + 512, 1024, 512, 1024, 0);
    bn_norm2<<<512, 256>>>(zr, g_e3, b_e3, st2, st2 + 512, 1024, z_0, z_1);

    // ---- vector quantization (finalize folded in) ----
    gemm_hh<1,1><<<grid6464(1024, 512), 256, DS11>>>(
        z_0, z_1, cb_0, cb_1, nullptr, sc, nullptr, nullptr,
        nullptr, nullptr, 1024, 512, 512, 0);
    vq_argmin<<<1024, 512>>>(sc, cn, cb, cb_0, cb_1,
                             zr, st2, st2 + 512, g_e3, b_e3,
                             q_0, q_1, cnt, loss, out, (long)out_size);

    // ---- decoder ----
    gemm_hh<1,1><<<grid6464(1024, 512), 256, DS11>>>(
        q_0, q_1, wqt_0, wqt_1, b_q, nullptr, d0_0, d0_1,
        nullptr, nullptr, 1024, 512, 512, 0);

    gemm_hh<1,1><<<grid6464(1024, 1024), 256, DS11>>>(
        d0_0, d0_1, wd1_0, wd1_1, nullptr, d1r, nullptr, nullptr,
        st3, st3 + 512, 1024, 1024, 512, 0);
    bn_norm2<<<1024, 256>>>(d1r, g_d1, b_d1, st3, st3 + 512, 2048, d1_0, d1_1);

    // d2: 64x128 tiles -> grid 384 (was 192 @128x128)
    gemm_hh<1,2><<<grid64128(2048, 1536), 256, DS12>>>(
        d1_0, d1_1, wd2_0, wd2_1, nullptr, d2r, nullptr, nullptr,
        st4, st4 + 512, 2048, 1536, 512, 0);
    bn_norm2<<<2048, 256>>>(d2r, g_d2, b_d2, st4, st4 + 512, 6144, d2_0, d2_1);

    gemm_hh<2,2><<<grid128(6144, 2560), 256, DS22>>>(
        d2_0, d2_1, wd3_0, wd3_1, nullptr, d3r, nullptr, nullptr,
        st5, st5 + 512, 6144, 2560, 512, 0);
    bn_norm2<<<2048, 256>>>(d3r, g_d3, b_d3, st5, st5 + 512, 30720, d3_0, d3_1);

    // ---- output GEMM -> recon ----
    gemm_hh<2,2><<<grid128(30720, 135), 256, DS22>>>(
        d3_0, d3_1, wot_0, wot_1, b_out, out, nullptr, nullptr,
        nullptr, nullptr, 30720, 135, 512, 0);
}